// round 10
// baseline (speedup 1.0000x reference)
#include <cuda_runtime.h>

// Problem constants (from reference)
#define NROWS   32768
#define NIN     204
#define LAT     1568
#define KCL     16
#define DSUB    5
#define PROJW   (KCL*DSUB)   // 80
#define NCAT    300          // 204 + 80 + 16
#define NCATP   304          // padded

// Output layout: x_bar | s | z | logits (flattened tuple order)
#define XBAR_OFF 0
#define S_OFF    (NROWS*NIN)                 // 6684672
#define Z_OFF    (S_OFF + NROWS*KCL)         // 7208960
#define LOG_OFF  (Z_OFF + (size_t)NROWS*LAT) // 58589184

// Scratch (device globals: no allocation allowed)
__device__ float g_Wcat[LAT * NCATP];          // packed dec_W|D|pc_W, zero-padded
__device__ float g_proj[(size_t)NROWS * PROJW];

// ---------------------------------------------------------------------------
// Pack dec_W [1568,204], D [1568,80], pc_W [1568,16] into Wcat [1568,304]
// ---------------------------------------------------------------------------
__global__ void pack_wcat_kernel(const float* __restrict__ decW,
                                 const float* __restrict__ D,
                                 const float* __restrict__ pcW) {
    int idx = blockIdx.x * blockDim.x + threadIdx.x;
    if (idx >= LAT * NCATP) return;
    int r = idx / NCATP;
    int c = idx - r * NCATP;
    float v = 0.0f;
    if (c < NIN)            v = decW[r * NIN + c];
    else if (c < NIN+PROJW) v = D[r * PROJW + (c - NIN)];
    else if (c < NCAT)      v = pcW[r * KCL + (c - NIN - PROJW)];
    g_Wcat[idx] = v;
}

// ---------------------------------------------------------------------------
// SGEMM core: C[128x128] tile, BK=8, 256 threads, 8x8 per-thread micro-tile.
// A: MxK row-major (lda=K), B: KxN row-major (ldb). Guards on all edges.
// MODE 0: out = A@B + bias  -> z region
// MODE 1: routed epilogue   -> x_bar / g_proj / logits
// ---------------------------------------------------------------------------
template<int MODE>
__global__ __launch_bounds__(256, 2)
void sgemm_kernel(const float* __restrict__ A, const float* __restrict__ B,
                  int M, int N, int K, int lda, int ldb,
                  const float* __restrict__ bias0,   // enc_b (MODE0) / dec_b (MODE1)
                  const float* __restrict__ bias1,   // pc_b  (MODE1)
                  float* __restrict__ out0,          // z (MODE0) / x_bar (MODE1)
                  float* __restrict__ out1)          // logits (MODE1)
{
    __shared__ float As[8][128];
    __shared__ float Bs[8][128];

    const int tid = threadIdx.x;
    const int tx = tid & 15;        // 0..15 -> column group
    const int ty = tid >> 4;        // 0..15 -> row group
    const int m0 = blockIdx.y * 128;
    const int n0 = blockIdx.x * 128;

    float acc[8][8];
#pragma unroll
    for (int i = 0; i < 8; ++i)
#pragma unroll
        for (int j = 0; j < 8; ++j) acc[i][j] = 0.0f;

    const int ktiles = (K + 7) >> 3;
    for (int t = 0; t < ktiles; ++t) {
        const int k0 = t << 3;
        // Load A tile (128x8), store transposed As[k][m]
#pragma unroll
        for (int i = 0; i < 4; ++i) {
            int li = tid + i * 256;         // 0..1023
            int row = li >> 3, col = li & 7;
            int gr = m0 + row, gc = k0 + col;
            float v = 0.0f;
            if (gr < M && gc < K) v = A[(size_t)gr * lda + gc];
            As[col][row] = v;
        }
        // Load B tile (8x128), coalesced along n
#pragma unroll
        for (int i = 0; i < 4; ++i) {
            int li = tid + i * 256;
            int r = li >> 7, c = li & 127;
            int gr = k0 + r, gc = n0 + c;
            float v = 0.0f;
            if (gr < K && gc < N) v = B[(size_t)gr * ldb + gc];
            Bs[r][c] = v;
        }
        __syncthreads();

#pragma unroll
        for (int kk = 0; kk < 8; ++kk) {
            float a[8], b[8];
#pragma unroll
            for (int i = 0; i < 8; ++i) a[i] = As[kk][ty * 8 + i];
#pragma unroll
            for (int j = 0; j < 8; ++j) b[j] = Bs[kk][tx * 8 + j];
#pragma unroll
            for (int i = 0; i < 8; ++i)
#pragma unroll
                for (int j = 0; j < 8; ++j)
                    acc[i][j] = fmaf(a[i], b[j], acc[i][j]);
        }
        __syncthreads();
    }

    // Epilogue
#pragma unroll
    for (int i = 0; i < 8; ++i) {
        const int gr = m0 + ty * 8 + i;
        if (gr >= M) continue;
#pragma unroll
        for (int j = 0; j < 8; ++j) {
            const int gc = n0 + tx * 8 + j;
            if (gc >= N) continue;
            float v = acc[i][j];
            if (MODE == 0) {
                out0[(size_t)gr * N + gc] = v + bias0[gc];
            } else {
                if (gc < NIN) {
                    out0[(size_t)gr * NIN + gc] = v + bias0[gc];
                } else if (gc < NIN + PROJW) {
                    g_proj[(size_t)gr * PROJW + (gc - NIN)] = v;
                } else if (gc < NCAT) {
                    out1[(size_t)gr * KCL + (gc - NIN - PROJW)] = v + bias1[gc - NIN - PROJW];
                }
                // gc in [300,304): padding, discard
            }
        }
    }
}

// ---------------------------------------------------------------------------
// Soft subspace assignment: per row, 16 groups of 5 squared-sums, affine,
// row-normalize. Reads g_proj, writes s.
// s_i = ((sum_j p_ij^2) + ETA*d) / ((ETA+1)*d), then s_i /= sum(s)
// ETA=5, d=5 -> (acc + 25) / 30
// ---------------------------------------------------------------------------
__global__ void s_kernel(float* __restrict__ s_out) {
    int row = blockIdx.x * blockDim.x + threadIdx.x;
    if (row >= NROWS) return;
    const float* p = g_proj + (size_t)row * PROJW;
    float sv[KCL];
    float tot = 0.0f;
#pragma unroll
    for (int i = 0; i < KCL; ++i) {
        float acc = 0.0f;
#pragma unroll
        for (int j = 0; j < DSUB; ++j) {
            float v = p[i * DSUB + j];
            acc = fmaf(v, v, acc);
        }
        float si = (acc + 25.0f) * (1.0f / 30.0f);
        sv[i] = si;
        tot += si;
    }
    float inv = 1.0f / tot;
#pragma unroll
    for (int i = 0; i < KCL; ++i)
        s_out[(size_t)row * KCL + i] = sv[i] * inv;
}

// ---------------------------------------------------------------------------
extern "C" void kernel_launch(void* const* d_in, const int* in_sizes, int n_in,
                              void* d_out, int out_size) {
    const float* x     = (const float*)d_in[0];   // [32768, 204]
    const float* enc_W = (const float*)d_in[1];   // [204, 1568]
    const float* enc_b = (const float*)d_in[2];   // [1568]
    const float* dec_W = (const float*)d_in[3];   // [1568, 204]
    const float* dec_b = (const float*)d_in[4];   // [204]
    const float* Dm    = (const float*)d_in[5];   // [1568, 80]
    const float* pc_W  = (const float*)d_in[6];   // [1568, 16]
    const float* pc_b  = (const float*)d_in[7];   // [16]
    // d_in[8] = d (scalar), compile-time constant here

    float* out   = (float*)d_out;
    float* xbar  = out + XBAR_OFF;
    float* s     = out + S_OFF;
    float* z     = out + Z_OFF;
    float* logit = out + LOG_OFF;

    // 1) pack concatenated weight matrix for the fused second GEMM
    {
        int total = LAT * NCATP;
        pack_wcat_kernel<<<(total + 255) / 256, 256>>>(dec_W, Dm, pc_W);
    }

    // 2) z = x @ enc_W + enc_b   (M=32768, N=1568, K=204)
    {
        dim3 grid((LAT + 127) / 128, NROWS / 128);
        sgemm_kernel<0><<<grid, 256>>>(x, enc_W, NROWS, LAT, NIN, NIN, LAT,
                                       enc_b, nullptr, z, nullptr);
    }

    // 3) fused: [x_bar | proj | logits] = z @ Wcat  (M=32768, N=304, K=1568)
    {
        float* wcat_ptr = nullptr;
        cudaGetSymbolAddress((void**)&wcat_ptr, g_Wcat);
        dim3 grid((NCATP + 127) / 128, NROWS / 128);
        sgemm_kernel<1><<<grid, 256>>>(z, wcat_ptr, NROWS, NCATP, LAT, LAT, NCATP,
                                       dec_b, pc_b, xbar, logit);
    }

    // 4) soft subspace assignment s from proj scratch
    {
        s_kernel<<<(NROWS + 255) / 256, 256>>>(s);
    }
}

// round 11
// speedup vs baseline: 2.5616x; 2.5616x over previous
#include <cuda_runtime.h>
#include <cuda_bf16.h>
#include <cstdint>

// ---------------- problem constants ----------------
#define NROWS 32768
#define NIN   204
#define LAT   1568
#define KCL   16
#define DSUB  5
#define PROJW 80          // KCL*DSUB
#define NCAT  300         // 204+80+16
#define NCATP 320         // padded to BN multiple
#define KPAD1 224         // K for GEMM1 (204 -> 224, multiple of 32)
#define NPAD1 1600        // N for GEMM1 (1568 -> 1600)

// output layout: x_bar | s | z | logits
#define S_OFF   ((size_t)NROWS*NIN)
#define Z_OFF   (S_OFF + (size_t)NROWS*KCL)
#define LOG_OFF (Z_OFF + (size_t)NROWS*LAT)

// ---------------- scratch (device globals; no allocation allowed) ----------
__device__ __nv_bfloat16 g_xhi[(size_t)NROWS * KPAD1];
__device__ __nv_bfloat16 g_xlo[(size_t)NROWS * KPAD1];
__device__ __nv_bfloat16 g_ewhi[KPAD1 * NPAD1];
__device__ __nv_bfloat16 g_ewlo[KPAD1 * NPAD1];
__device__ __nv_bfloat16 g_zhi[(size_t)NROWS * LAT];
__device__ __nv_bfloat16 g_zlo[(size_t)NROWS * LAT];
__device__ __nv_bfloat16 g_wchi[LAT * NCATP];
__device__ __nv_bfloat16 g_wclo[LAT * NCATP];
__device__ float         g_proj[(size_t)NROWS * PROJW];

// ---------------- helpers ----------------
__device__ __forceinline__ void split_bf16(float v, __nv_bfloat16& h, __nv_bfloat16& l) {
    h = __float2bfloat16(v);
    l = __float2bfloat16(v - __bfloat162float(h));
}

__device__ __forceinline__ void cpa16(uint32_t dst, const void* src) {
    asm volatile("cp.async.cg.shared.global [%0], [%1], 16;\n" :: "r"(dst), "l"(src));
}

__device__ __forceinline__ void ldmA(uint32_t* r, uint32_t addr) {
    asm volatile("ldmatrix.sync.aligned.m8n8.x4.shared.b16 {%0,%1,%2,%3}, [%4];\n"
                 : "=r"(r[0]), "=r"(r[1]), "=r"(r[2]), "=r"(r[3]) : "r"(addr));
}
__device__ __forceinline__ void ldmBt(uint32_t* r, uint32_t addr) {
    asm volatile("ldmatrix.sync.aligned.m8n8.x2.trans.shared.b16 {%0,%1}, [%2];\n"
                 : "=r"(r[0]), "=r"(r[1]) : "r"(addr));
}
__device__ __forceinline__ void mma16816(float* c, const uint32_t* a, const uint32_t* b) {
    asm volatile("mma.sync.aligned.m16n8k16.row.col.f32.bf16.bf16.f32 "
                 "{%0,%1,%2,%3}, {%4,%5,%6,%7}, {%8,%9}, {%0,%1,%2,%3};\n"
                 : "+f"(c[0]), "+f"(c[1]), "+f"(c[2]), "+f"(c[3])
                 : "r"(a[0]), "r"(a[1]), "r"(a[2]), "r"(a[3]), "r"(b[0]), "r"(b[1]));
}

// ---------------- conversion / packing kernels ----------------
__global__ void conv_x_kernel(const float* __restrict__ x) {
    int idx = blockIdx.x * blockDim.x + threadIdx.x;
    if (idx >= NROWS * KPAD1) return;
    int r = idx / KPAD1, c = idx - r * KPAD1;
    float v = (c < NIN) ? x[(size_t)r * NIN + c] : 0.0f;
    split_bf16(v, g_xhi[idx], g_xlo[idx]);
}

__global__ void conv_ew_kernel(const float* __restrict__ w) {
    int idx = blockIdx.x * blockDim.x + threadIdx.x;
    if (idx >= KPAD1 * NPAD1) return;
    int r = idx / NPAD1, c = idx - r * NPAD1;
    float v = (r < NIN && c < LAT) ? w[(size_t)r * LAT + c] : 0.0f;
    split_bf16(v, g_ewhi[idx], g_ewlo[idx]);
}

__global__ void conv_wc_kernel(const float* __restrict__ decW,
                               const float* __restrict__ D,
                               const float* __restrict__ pcW) {
    int idx = blockIdx.x * blockDim.x + threadIdx.x;
    if (idx >= LAT * NCATP) return;
    int r = idx / NCATP, c = idx - r * NCATP;
    float v = 0.0f;
    if (c < NIN)              v = decW[(size_t)r * NIN + c];
    else if (c < NIN + PROJW) v = D[(size_t)r * PROJW + (c - NIN)];
    else if (c < NCAT)        v = pcW[(size_t)r * KCL + (c - NIN - PROJW)];
    split_bf16(v, g_wchi[idx], g_wclo[idx]);
}

// ---------------- GEMM: BM=128 BN=64 BK=32, 256 threads, bf16 3-split -------
#define BM 128
#define BN 64
#define BK 32
#define APITCH 80u        // bytes/row smem A (64B data + 16B pad) -> ldmatrix conflict-free
#define BPITCH 144u       // bytes/row smem B (128B data + 16B pad)
#define A_BYTES (BM * APITCH)                  // 10240
#define B_BYTES (BK * BPITCH)                  // 4608
#define STAGE_BYTES (2u * A_BYTES + 2u * B_BYTES)  // 29696

__device__ __forceinline__ void load_stage(
    uint32_t sbuf,
    const __nv_bfloat16* __restrict__ Ahi, const __nv_bfloat16* __restrict__ Alo,
    const __nv_bfloat16* __restrict__ Bhi, const __nv_bfloat16* __restrict__ Blo,
    int m0, int n0, int k0, int ldA, int ldB, int tid)
{
    uint32_t sAhi = sbuf;
    uint32_t sAlo = sbuf + A_BYTES;
    uint32_t sBhi = sbuf + 2u * A_BYTES;
    uint32_t sBlo = sBhi + B_BYTES;

    // A tile: 128 rows x 32 bf16 (64B) -> 4 x 16B chunks/row, 512 chunks/split
#pragma unroll
    for (int i = 0; i < 2; ++i) {
        int c = tid + i * 256;
        int row = c >> 2;
        uint32_t cb = (uint32_t)(c & 3) << 4;
        size_t goff = ((size_t)(m0 + row) * ldA + k0) * 2 + cb;
        cpa16(sAhi + (uint32_t)row * APITCH + cb, (const char*)Ahi + goff);
        cpa16(sAlo + (uint32_t)row * APITCH + cb, (const char*)Alo + goff);
    }
    // B tile: 32 rows x 64 bf16 (128B) -> 8 chunks/row, 256 chunks/split
    {
        int row = tid >> 3;
        uint32_t cb = (uint32_t)(tid & 7) << 4;
        size_t goff = ((size_t)(k0 + row) * ldB + n0) * 2 + cb;
        cpa16(sBhi + (uint32_t)row * BPITCH + cb, (const char*)Bhi + goff);
        cpa16(sBlo + (uint32_t)row * BPITCH + cb, (const char*)Blo + goff);
    }
    asm volatile("cp.async.commit_group;\n");
}

// MODE 0: z = A@B + enc_b  -> out0 (fp32, ld=LAT, guard n<LAT) + split into g_zhi/g_zlo
// MODE 1: routed: n<204 -> x_bar(+dec_b); 204..283 -> g_proj; 284..299 -> logits(+pc_b)
template<int MODE>
__global__ __launch_bounds__(256)
void mma_gemm(const __nv_bfloat16* __restrict__ Ahi, const __nv_bfloat16* __restrict__ Alo,
              const __nv_bfloat16* __restrict__ Bhi, const __nv_bfloat16* __restrict__ Blo,
              int K, int ldA, int ldB,
              const float* __restrict__ bias0, const float* __restrict__ bias1,
              float* __restrict__ out0, float* __restrict__ out1)
{
    extern __shared__ char smem_raw[];
    const uint32_t sbase = (uint32_t)__cvta_generic_to_shared(smem_raw);

    const int tid  = threadIdx.x;
    const int lane = tid & 31;
    const int warp = tid >> 5;
    const int wm   = warp >> 2;   // 0..1 -> 64-row half
    const int wn   = warp & 3;    // 0..3 -> 16-col slice
    const int m0   = blockIdx.y * BM;
    const int n0   = blockIdx.x * BN;

    float acc[4][2][4];
#pragma unroll
    for (int i = 0; i < 4; ++i)
#pragma unroll
        for (int j = 0; j < 2; ++j)
#pragma unroll
            for (int e = 0; e < 4; ++e) acc[i][j][e] = 0.0f;

    const int T = K / BK;
    load_stage(sbase, Ahi, Alo, Bhi, Blo, m0, n0, 0, ldA, ldB, tid);

    for (int t = 0; t < T; ++t) {
        asm volatile("cp.async.wait_group 0;\n");
        __syncthreads();
        if (t + 1 < T)
            load_stage(sbase + ((uint32_t)((t + 1) & 1)) * STAGE_BYTES,
                       Ahi, Alo, Bhi, Blo, m0, n0, (t + 1) * BK, ldA, ldB, tid);

        const uint32_t sbuf = sbase + ((uint32_t)(t & 1)) * STAGE_BYTES;
        const uint32_t sAhi = sbuf;
        const uint32_t sAlo = sbuf + A_BYTES;
        const uint32_t sBhi = sbuf + 2u * A_BYTES;
        const uint32_t sBlo = sBhi + B_BYTES;

#pragma unroll
        for (int kk = 0; kk < 2; ++kk) {
            uint32_t ahi[4][4], alo[4][4], bhi[2][2], blo[2][2];
            // A fragments: lanes 0-7 rows0-7@klo, 8-15 rows8-15@klo, 16-23 rows0-7@khi, 24-31 rows8-15@khi
            const uint32_t arow = (uint32_t)(wm * 64 + (lane & 15));
            const uint32_t acol = ((uint32_t)(lane >> 4) << 4) + (uint32_t)kk * 32u;
#pragma unroll
            for (int mt = 0; mt < 4; ++mt) {
                uint32_t off = (arow + (uint32_t)mt * 16u) * APITCH + acol;
                ldmA(ahi[mt], sAhi + off);
                ldmA(alo[mt], sAlo + off);
            }
            // B fragments (trans): lanes 0-15 supply k rows
            const uint32_t brow = (uint32_t)(kk * 16 + (lane & 15));
#pragma unroll
            for (int nt = 0; nt < 2; ++nt) {
                uint32_t off = brow * BPITCH + (uint32_t)(wn * 32 + nt * 16);
                ldmBt(bhi[nt], sBhi + off);
                ldmBt(blo[nt], sBlo + off);
            }
#pragma unroll
            for (int mt = 0; mt < 4; ++mt)
#pragma unroll
                for (int nt = 0; nt < 2; ++nt) {
                    mma16816(acc[mt][nt], ahi[mt], bhi[nt]);
                    mma16816(acc[mt][nt], ahi[mt], blo[nt]);
                    mma16816(acc[mt][nt], alo[mt], bhi[nt]);
                }
        }
        __syncthreads();
    }

    // ---- epilogue ----
#pragma unroll
    for (int mt = 0; mt < 4; ++mt) {
        const int row0 = m0 + wm * 64 + mt * 16 + (lane >> 2);
#pragma unroll
        for (int nt = 0; nt < 2; ++nt) {
            const int col0 = n0 + wn * 16 + nt * 8 + (lane & 3) * 2;
#pragma unroll
            for (int e = 0; e < 4; ++e) {
                const int row = row0 + (e >> 1) * 8;
                const int col = col0 + (e & 1);
                const float v = acc[mt][nt][e];
                if (MODE == 0) {
                    if (col < LAT) {
                        float z = v + bias0[col];
                        size_t idx = (size_t)row * LAT + col;
                        out0[idx] = z;
                        split_bf16(z, g_zhi[idx], g_zlo[idx]);
                    }
                } else {
                    if (col < NIN) {
                        out0[(size_t)row * NIN + col] = v + bias0[col];
                    } else if (col < NIN + PROJW) {
                        g_proj[(size_t)row * PROJW + (col - NIN)] = v;
                    } else if (col < NCAT) {
                        out1[(size_t)row * KCL + (col - NIN - PROJW)] = v + bias1[col - NIN - PROJW];
                    }
                }
            }
        }
    }
}

// ---------------- soft subspace assignment ----------------
__global__ void s_kernel(float* __restrict__ s_out) {
    int row = blockIdx.x * blockDim.x + threadIdx.x;
    if (row >= NROWS) return;
    const float* p = g_proj + (size_t)row * PROJW;
    float sv[KCL];
    float tot = 0.0f;
#pragma unroll
    for (int i = 0; i < KCL; ++i) {
        float a = 0.0f;
#pragma unroll
        for (int j = 0; j < DSUB; ++j) {
            float v = p[i * DSUB + j];
            a = fmaf(v, v, a);
        }
        float si = (a + 25.0f) * (1.0f / 30.0f);   // (s + ETA*d)/((ETA+1)*d), ETA=5,d=5
        sv[i] = si;
        tot += si;
    }
    float inv = 1.0f / tot;
#pragma unroll
    for (int i = 0; i < KCL; ++i)
        s_out[(size_t)row * KCL + i] = sv[i] * inv;
}

// ---------------- launch ----------------
extern "C" void kernel_launch(void* const* d_in, const int* in_sizes, int n_in,
                              void* d_out, int out_size) {
    const float* x     = (const float*)d_in[0];
    const float* enc_W = (const float*)d_in[1];
    const float* enc_b = (const float*)d_in[2];
    const float* dec_W = (const float*)d_in[3];
    const float* dec_b = (const float*)d_in[4];
    const float* Dm    = (const float*)d_in[5];
    const float* pc_W  = (const float*)d_in[6];
    const float* pc_b  = (const float*)d_in[7];

    float* out   = (float*)d_out;
    float* xbar  = out;
    float* s     = out + S_OFF;
    float* z     = out + Z_OFF;
    float* logit = out + LOG_OFF;

    // scratch symbol addresses (host-side, capture-safe)
    __nv_bfloat16 *xhi, *xlo, *ewhi, *ewlo, *zhi, *zlo, *wchi, *wclo;
    cudaGetSymbolAddress((void**)&xhi,  g_xhi);
    cudaGetSymbolAddress((void**)&xlo,  g_xlo);
    cudaGetSymbolAddress((void**)&ewhi, g_ewhi);
    cudaGetSymbolAddress((void**)&ewlo, g_ewlo);
    cudaGetSymbolAddress((void**)&zhi,  g_zhi);
    cudaGetSymbolAddress((void**)&zlo,  g_zlo);
    cudaGetSymbolAddress((void**)&wchi, g_wchi);
    cudaGetSymbolAddress((void**)&wclo, g_wclo);

    cudaFuncSetAttribute(mma_gemm<0>, cudaFuncAttributeMaxDynamicSharedMemorySize, 2 * STAGE_BYTES);
    cudaFuncSetAttribute(mma_gemm<1>, cudaFuncAttributeMaxDynamicSharedMemorySize, 2 * STAGE_BYTES);

    // 1) split/pack operands to bf16 hi/lo
    conv_x_kernel<<<(NROWS * KPAD1 + 255) / 256, 256>>>(x);
    conv_ew_kernel<<<(KPAD1 * NPAD1 + 255) / 256, 256>>>(enc_W);
    conv_wc_kernel<<<(LAT * NCATP + 255) / 256, 256>>>(dec_W, Dm, pc_W);

    // 2) z = x @ enc_W + enc_b  (M=32768, N=1600(pad), K=224(pad))
    {
        dim3 grid(NPAD1 / BN, NROWS / BM);
        mma_gemm<0><<<grid, 256, 2 * STAGE_BYTES>>>(
            xhi, xlo, ewhi, ewlo, KPAD1, KPAD1, NPAD1,
            enc_b, nullptr, z, nullptr);
    }

    // 3) [x_bar | proj | logits] = z @ Wcat  (M=32768, N=320(pad), K=1568)
    {
        dim3 grid(NCATP / BN, NROWS / BM);
        mma_gemm<1><<<grid, 256, 2 * STAGE_BYTES>>>(
            zhi, zlo, wchi, wclo, LAT, LAT, NCATP,
            dec_b, pc_b, xbar, logit);
    }

    // 4) s from proj
    s_kernel<<<(NROWS + 255) / 256, 256>>>(s);
}

// round 12
// speedup vs baseline: 2.5653x; 1.0014x over previous
#include <cuda_runtime.h>
#include <cuda_bf16.h>
#include <cstdint>

// ---------------- problem constants ----------------
#define NROWS 32768
#define NIN   204
#define LAT   1568
#define KCL   16
#define DSUB  5
#define PROJW 80          // KCL*DSUB
#define NCAT  300         // 204+80+16
#define NCATP 320         // padded to BN multiple
#define KPAD1 224         // K for GEMM1 (204 -> 224, multiple of 32)
#define NPAD1 1600        // N for GEMM1 (1568 -> 1600)

// output layout: x_bar | s | z | logits
#define S_OFF   ((size_t)NROWS*NIN)
#define Z_OFF   (S_OFF + (size_t)NROWS*KCL)
#define LOG_OFF (Z_OFF + (size_t)NROWS*LAT)

// ---------------- scratch (device globals; no allocation allowed) ----------
__device__ __nv_bfloat16 g_xhi[(size_t)NROWS * KPAD1];
__device__ __nv_bfloat16 g_xlo[(size_t)NROWS * KPAD1];
__device__ __nv_bfloat16 g_ewhi[KPAD1 * NPAD1];
__device__ __nv_bfloat16 g_ewlo[KPAD1 * NPAD1];
__device__ __nv_bfloat16 g_zhi[(size_t)NROWS * LAT];
__device__ __nv_bfloat16 g_zlo[(size_t)NROWS * LAT];
__device__ __nv_bfloat16 g_wchi[LAT * NCATP];
__device__ __nv_bfloat16 g_wclo[LAT * NCATP];
__device__ float         g_proj[(size_t)NROWS * PROJW];

// ---------------- helpers ----------------
__device__ __forceinline__ void split_bf16(float v, __nv_bfloat16& h, __nv_bfloat16& l) {
    h = __float2bfloat16(v);
    l = __float2bfloat16(v - __bfloat162float(h));
}

__device__ __forceinline__ void cpa16(uint32_t dst, const void* src) {
    asm volatile("cp.async.cg.shared.global [%0], [%1], 16;\n" :: "r"(dst), "l"(src));
}

__device__ __forceinline__ void ldmA(uint32_t* r, uint32_t addr) {
    asm volatile("ldmatrix.sync.aligned.m8n8.x4.shared.b16 {%0,%1,%2,%3}, [%4];\n"
                 : "=r"(r[0]), "=r"(r[1]), "=r"(r[2]), "=r"(r[3]) : "r"(addr));
}
__device__ __forceinline__ void ldmBt(uint32_t* r, uint32_t addr) {
    asm volatile("ldmatrix.sync.aligned.m8n8.x2.trans.shared.b16 {%0,%1}, [%2];\n"
                 : "=r"(r[0]), "=r"(r[1]) : "r"(addr));
}
__device__ __forceinline__ void mma16816(float* c, const uint32_t* a, const uint32_t* b) {
    asm volatile("mma.sync.aligned.m16n8k16.row.col.f32.bf16.bf16.f32 "
                 "{%0,%1,%2,%3}, {%4,%5,%6,%7}, {%8,%9}, {%0,%1,%2,%3};\n"
                 : "+f"(c[0]), "+f"(c[1]), "+f"(c[2]), "+f"(c[3])
                 : "r"(a[0]), "r"(a[1]), "r"(a[2]), "r"(a[3]), "r"(b[0]), "r"(b[1]));
}

// ---------------- conversion / packing kernels ----------------
__global__ void conv_x_kernel(const float* __restrict__ x) {
    int idx = blockIdx.x * blockDim.x + threadIdx.x;
    if (idx >= NROWS * KPAD1) return;
    int r = idx / KPAD1, c = idx - r * KPAD1;
    float v = (c < NIN) ? x[(size_t)r * NIN + c] : 0.0f;
    split_bf16(v, g_xhi[idx], g_xlo[idx]);
}

__global__ void conv_ew_kernel(const float* __restrict__ w) {
    int idx = blockIdx.x * blockDim.x + threadIdx.x;
    if (idx >= KPAD1 * NPAD1) return;
    int r = idx / NPAD1, c = idx - r * NPAD1;
    float v = (r < NIN && c < LAT) ? w[(size_t)r * LAT + c] : 0.0f;
    split_bf16(v, g_ewhi[idx], g_ewlo[idx]);
}

__global__ void conv_wc_kernel(const float* __restrict__ decW,
                               const float* __restrict__ D,
                               const float* __restrict__ pcW) {
    int idx = blockIdx.x * blockDim.x + threadIdx.x;
    if (idx >= LAT * NCATP) return;
    int r = idx / NCATP, c = idx - r * NCATP;
    float v = 0.0f;
    if (c < NIN)              v = decW[(size_t)r * NIN + c];
    else if (c < NIN + PROJW) v = D[(size_t)r * PROJW + (c - NIN)];
    else if (c < NCAT)        v = pcW[(size_t)r * KCL + (c - NIN - PROJW)];
    split_bf16(v, g_wchi[idx], g_wclo[idx]);
}

// ---------------- GEMM: BM=128 BN=64 BK=32, 256 threads, bf16 3-split -------
#define BM 128
#define BN 64
#define BK 32
#define APITCH 80u        // bytes/row smem A (64B data + 16B pad) -> ldmatrix conflict-free
#define BPITCH 144u       // bytes/row smem B (128B data + 16B pad)
#define A_BYTES (BM * APITCH)                  // 10240
#define B_BYTES (BK * BPITCH)                  // 4608
#define STAGE_BYTES (2u * A_BYTES + 2u * B_BYTES)  // 29696

__device__ __forceinline__ void load_stage(
    uint32_t sbuf,
    const __nv_bfloat16* __restrict__ Ahi, const __nv_bfloat16* __restrict__ Alo,
    const __nv_bfloat16* __restrict__ Bhi, const __nv_bfloat16* __restrict__ Blo,
    int m0, int n0, int k0, int ldA, int ldB, int tid)
{
    uint32_t sAhi = sbuf;
    uint32_t sAlo = sbuf + A_BYTES;
    uint32_t sBhi = sbuf + 2u * A_BYTES;
    uint32_t sBlo = sBhi + B_BYTES;

    // A tile: 128 rows x 32 bf16 (64B) -> 4 x 16B chunks/row, 512 chunks/split
#pragma unroll
    for (int i = 0; i < 2; ++i) {
        int c = tid + i * 256;
        int row = c >> 2;
        uint32_t cb = (uint32_t)(c & 3) << 4;
        size_t goff = ((size_t)(m0 + row) * ldA + k0) * 2 + cb;
        cpa16(sAhi + (uint32_t)row * APITCH + cb, (const char*)Ahi + goff);
        cpa16(sAlo + (uint32_t)row * APITCH + cb, (const char*)Alo + goff);
    }
    // B tile: 32 rows x 64 bf16 (128B) -> 8 chunks/row, 256 chunks/split
    {
        int row = tid >> 3;
        uint32_t cb = (uint32_t)(tid & 7) << 4;
        size_t goff = ((size_t)(k0 + row) * ldB + n0) * 2 + cb;
        cpa16(sBhi + (uint32_t)row * BPITCH + cb, (const char*)Bhi + goff);
        cpa16(sBlo + (uint32_t)row * BPITCH + cb, (const char*)Blo + goff);
    }
    asm volatile("cp.async.commit_group;\n");
}

// MODE 0: z = A@B + enc_b  -> out0 (fp32, ld=LAT, guard n<LAT) + split into g_zhi/g_zlo
// MODE 1: routed: n<204 -> x_bar(+dec_b); 204..283 -> g_proj; 284..299 -> logits(+pc_b)
template<int MODE>
__global__ __launch_bounds__(256)
void mma_gemm(const __nv_bfloat16* __restrict__ Ahi, const __nv_bfloat16* __restrict__ Alo,
              const __nv_bfloat16* __restrict__ Bhi, const __nv_bfloat16* __restrict__ Blo,
              int K, int ldA, int ldB,
              const float* __restrict__ bias0, const float* __restrict__ bias1,
              float* __restrict__ out0, float* __restrict__ out1)
{
    extern __shared__ char smem_raw[];
    const uint32_t sbase = (uint32_t)__cvta_generic_to_shared(smem_raw);

    const int tid  = threadIdx.x;
    const int lane = tid & 31;
    const int warp = tid >> 5;
    const int wm   = warp >> 2;   // 0..1 -> 64-row half
    const int wn   = warp & 3;    // 0..3 -> 16-col slice
    const int m0   = blockIdx.y * BM;
    const int n0   = blockIdx.x * BN;

    float acc[4][2][4];
#pragma unroll
    for (int i = 0; i < 4; ++i)
#pragma unroll
        for (int j = 0; j < 2; ++j)
#pragma unroll
            for (int e = 0; e < 4; ++e) acc[i][j][e] = 0.0f;

    const int T = K / BK;
    load_stage(sbase, Ahi, Alo, Bhi, Blo, m0, n0, 0, ldA, ldB, tid);

    for (int t = 0; t < T; ++t) {
        asm volatile("cp.async.wait_group 0;\n");
        __syncthreads();
        if (t + 1 < T)
            load_stage(sbase + ((uint32_t)((t + 1) & 1)) * STAGE_BYTES,
                       Ahi, Alo, Bhi, Blo, m0, n0, (t + 1) * BK, ldA, ldB, tid);

        const uint32_t sbuf = sbase + ((uint32_t)(t & 1)) * STAGE_BYTES;
        const uint32_t sAhi = sbuf;
        const uint32_t sAlo = sbuf + A_BYTES;
        const uint32_t sBhi = sbuf + 2u * A_BYTES;
        const uint32_t sBlo = sBhi + B_BYTES;

#pragma unroll
        for (int kk = 0; kk < 2; ++kk) {
            uint32_t ahi[4][4], alo[4][4], bhi[2][2], blo[2][2];
            // A fragments: lanes 0-7 rows0-7@klo, 8-15 rows8-15@klo, 16-23 rows0-7@khi, 24-31 rows8-15@khi
            const uint32_t arow = (uint32_t)(wm * 64 + (lane & 15));
            const uint32_t acol = ((uint32_t)(lane >> 4) << 4) + (uint32_t)kk * 32u;
#pragma unroll
            for (int mt = 0; mt < 4; ++mt) {
                uint32_t off = (arow + (uint32_t)mt * 16u) * APITCH + acol;
                ldmA(ahi[mt], sAhi + off);
                ldmA(alo[mt], sAlo + off);
            }
            // B fragments (trans): lanes 0-15 supply k rows
            const uint32_t brow = (uint32_t)(kk * 16 + (lane & 15));
#pragma unroll
            for (int nt = 0; nt < 2; ++nt) {
                uint32_t off = brow * BPITCH + (uint32_t)(wn * 32 + nt * 16);
                ldmBt(bhi[nt], sBhi + off);
                ldmBt(blo[nt], sBlo + off);
            }
#pragma unroll
            for (int mt = 0; mt < 4; ++mt)
#pragma unroll
                for (int nt = 0; nt < 2; ++nt) {
                    mma16816(acc[mt][nt], ahi[mt], bhi[nt]);
                    mma16816(acc[mt][nt], ahi[mt], blo[nt]);
                    mma16816(acc[mt][nt], alo[mt], bhi[nt]);
                }
        }
        __syncthreads();
    }

    // ---- epilogue ----
#pragma unroll
    for (int mt = 0; mt < 4; ++mt) {
        const int row0 = m0 + wm * 64 + mt * 16 + (lane >> 2);
#pragma unroll
        for (int nt = 0; nt < 2; ++nt) {
            const int col0 = n0 + wn * 16 + nt * 8 + (lane & 3) * 2;
#pragma unroll
            for (int e = 0; e < 4; ++e) {
                const int row = row0 + (e >> 1) * 8;
                const int col = col0 + (e & 1);
                const float v = acc[mt][nt][e];
                if (MODE == 0) {
                    if (col < LAT) {
                        float z = v + bias0[col];
                        size_t idx = (size_t)row * LAT + col;
                        out0[idx] = z;
                        split_bf16(z, g_zhi[idx], g_zlo[idx]);
                    }
                } else {
                    if (col < NIN) {
                        out0[(size_t)row * NIN + col] = v + bias0[col];
                    } else if (col < NIN + PROJW) {
                        g_proj[(size_t)row * PROJW + (col - NIN)] = v;
                    } else if (col < NCAT) {
                        out1[(size_t)row * KCL + (col - NIN - PROJW)] = v + bias1[col - NIN - PROJW];
                    }
                }
            }
        }
    }
}

// ---------------- soft subspace assignment ----------------
__global__ void s_kernel(float* __restrict__ s_out) {
    int row = blockIdx.x * blockDim.x + threadIdx.x;
    if (row >= NROWS) return;
    const float* p = g_proj + (size_t)row * PROJW;
    float sv[KCL];
    float tot = 0.0f;
#pragma unroll
    for (int i = 0; i < KCL; ++i) {
        float a = 0.0f;
#pragma unroll
        for (int j = 0; j < DSUB; ++j) {
            float v = p[i * DSUB + j];
            a = fmaf(v, v, a);
        }
        float si = (a + 25.0f) * (1.0f / 30.0f);   // (s + ETA*d)/((ETA+1)*d), ETA=5,d=5
        sv[i] = si;
        tot += si;
    }
    float inv = 1.0f / tot;
#pragma unroll
    for (int i = 0; i < KCL; ++i)
        s_out[(size_t)row * KCL + i] = sv[i] * inv;
}

// ---------------- launch ----------------
extern "C" void kernel_launch(void* const* d_in, const int* in_sizes, int n_in,
                              void* d_out, int out_size) {
    const float* x     = (const float*)d_in[0];
    const float* enc_W = (const float*)d_in[1];
    const float* enc_b = (const float*)d_in[2];
    const float* dec_W = (const float*)d_in[3];
    const float* dec_b = (const float*)d_in[4];
    const float* Dm    = (const float*)d_in[5];
    const float* pc_W  = (const float*)d_in[6];
    const float* pc_b  = (const float*)d_in[7];

    float* out   = (float*)d_out;
    float* xbar  = out;
    float* s     = out + S_OFF;
    float* z     = out + Z_OFF;
    float* logit = out + LOG_OFF;

    // scratch symbol addresses (host-side, capture-safe)
    __nv_bfloat16 *xhi, *xlo, *ewhi, *ewlo, *zhi, *zlo, *wchi, *wclo;
    cudaGetSymbolAddress((void**)&xhi,  g_xhi);
    cudaGetSymbolAddress((void**)&xlo,  g_xlo);
    cudaGetSymbolAddress((void**)&ewhi, g_ewhi);
    cudaGetSymbolAddress((void**)&ewlo, g_ewlo);
    cudaGetSymbolAddress((void**)&zhi,  g_zhi);
    cudaGetSymbolAddress((void**)&zlo,  g_zlo);
    cudaGetSymbolAddress((void**)&wchi, g_wchi);
    cudaGetSymbolAddress((void**)&wclo, g_wclo);

    cudaFuncSetAttribute(mma_gemm<0>, cudaFuncAttributeMaxDynamicSharedMemorySize, 2 * STAGE_BYTES);
    cudaFuncSetAttribute(mma_gemm<1>, cudaFuncAttributeMaxDynamicSharedMemorySize, 2 * STAGE_BYTES);

    // 1) split/pack operands to bf16 hi/lo
    conv_x_kernel<<<(NROWS * KPAD1 + 255) / 256, 256>>>(x);
    conv_ew_kernel<<<(KPAD1 * NPAD1 + 255) / 256, 256>>>(enc_W);
    conv_wc_kernel<<<(LAT * NCATP + 255) / 256, 256>>>(dec_W, Dm, pc_W);

    // 2) z = x @ enc_W + enc_b  (M=32768, N=1600(pad), K=224(pad))
    {
        dim3 grid(NPAD1 / BN, NROWS / BM);
        mma_gemm<0><<<grid, 256, 2 * STAGE_BYTES>>>(
            xhi, xlo, ewhi, ewlo, KPAD1, KPAD1, NPAD1,
            enc_b, nullptr, z, nullptr);
    }

    // 3) [x_bar | proj | logits] = z @ Wcat  (M=32768, N=320(pad), K=1568)
    {
        dim3 grid(NCATP / BN, NROWS / BM);
        mma_gemm<1><<<grid, 256, 2 * STAGE_BYTES>>>(
            zhi, zlo, wchi, wclo, LAT, LAT, NCATP,
            dec_b, pc_b, xbar, logit);
    }

    // 4) s from proj
    s_kernel<<<(NROWS + 255) / 256, 256>>>(s);
}

// round 13
// speedup vs baseline: 2.5659x; 1.0003x over previous
#include <cuda_runtime.h>
#include <cuda_bf16.h>
#include <cstdint>

// ---------------- problem constants ----------------
#define NROWS 32768
#define NIN   204
#define LAT   1568
#define KCL   16
#define DSUB  5
#define PROJW 80          // KCL*DSUB
#define NCAT  300         // 204+80+16
#define NCATP 320         // padded to BN multiple
#define KPAD1 224         // K for GEMM1 (204 -> 224, multiple of 32)
#define NPAD1 1600        // N for GEMM1 (1568 -> 1600)

// output layout: x_bar | s | z | logits
#define S_OFF   ((size_t)NROWS*NIN)
#define Z_OFF   (S_OFF + (size_t)NROWS*KCL)
#define LOG_OFF (Z_OFF + (size_t)NROWS*LAT)

// ---------------- scratch (device globals; no allocation allowed) ----------
__device__ __nv_bfloat16 g_xhi[(size_t)NROWS * KPAD1];
__device__ __nv_bfloat16 g_xlo[(size_t)NROWS * KPAD1];
__device__ __nv_bfloat16 g_ewhi[KPAD1 * NPAD1];
__device__ __nv_bfloat16 g_ewlo[KPAD1 * NPAD1];
__device__ __nv_bfloat16 g_zhi[(size_t)NROWS * LAT];
__device__ __nv_bfloat16 g_zlo[(size_t)NROWS * LAT];
__device__ __nv_bfloat16 g_wchi[LAT * NCATP];
__device__ __nv_bfloat16 g_wclo[LAT * NCATP];
__device__ float         g_proj[(size_t)NROWS * PROJW];

// ---------------- helpers ----------------
__device__ __forceinline__ void split_bf16(float v, __nv_bfloat16& h, __nv_bfloat16& l) {
    h = __float2bfloat16(v);
    l = __float2bfloat16(v - __bfloat162float(h));
}

__device__ __forceinline__ void cpa16(uint32_t dst, const void* src) {
    asm volatile("cp.async.cg.shared.global [%0], [%1], 16;\n" :: "r"(dst), "l"(src));
}

__device__ __forceinline__ void ldmA(uint32_t* r, uint32_t addr) {
    asm volatile("ldmatrix.sync.aligned.m8n8.x4.shared.b16 {%0,%1,%2,%3}, [%4];\n"
                 : "=r"(r[0]), "=r"(r[1]), "=r"(r[2]), "=r"(r[3]) : "r"(addr));
}
__device__ __forceinline__ void ldmBt(uint32_t* r, uint32_t addr) {
    asm volatile("ldmatrix.sync.aligned.m8n8.x2.trans.shared.b16 {%0,%1}, [%2];\n"
                 : "=r"(r[0]), "=r"(r[1]) : "r"(addr));
}
__device__ __forceinline__ void mma16816(float* c, const uint32_t* a, const uint32_t* b) {
    asm volatile("mma.sync.aligned.m16n8k16.row.col.f32.bf16.bf16.f32 "
                 "{%0,%1,%2,%3}, {%4,%5,%6,%7}, {%8,%9}, {%0,%1,%2,%3};\n"
                 : "+f"(c[0]), "+f"(c[1]), "+f"(c[2]), "+f"(c[3])
                 : "r"(a[0]), "r"(a[1]), "r"(a[2]), "r"(a[3]), "r"(b[0]), "r"(b[1]));
}

// ---------------- conversion / packing kernels ----------------
__global__ void conv_x_kernel(const float* __restrict__ x) {
    int idx = blockIdx.x * blockDim.x + threadIdx.x;
    if (idx >= NROWS * KPAD1) return;
    int r = idx / KPAD1, c = idx - r * KPAD1;
    float v = (c < NIN) ? x[(size_t)r * NIN + c] : 0.0f;
    split_bf16(v, g_xhi[idx], g_xlo[idx]);
}

__global__ void conv_ew_kernel(const float* __restrict__ w) {
    int idx = blockIdx.x * blockDim.x + threadIdx.x;
    if (idx >= KPAD1 * NPAD1) return;
    int r = idx / NPAD1, c = idx - r * NPAD1;
    float v = (r < NIN && c < LAT) ? w[(size_t)r * LAT + c] : 0.0f;
    split_bf16(v, g_ewhi[idx], g_ewlo[idx]);
}

__global__ void conv_wc_kernel(const float* __restrict__ decW,
                               const float* __restrict__ D,
                               const float* __restrict__ pcW) {
    int idx = blockIdx.x * blockDim.x + threadIdx.x;
    if (idx >= LAT * NCATP) return;
    int r = idx / NCATP, c = idx - r * NCATP;
    float v = 0.0f;
    if (c < NIN)              v = decW[(size_t)r * NIN + c];
    else if (c < NIN + PROJW) v = D[(size_t)r * PROJW + (c - NIN)];
    else if (c < NCAT)        v = pcW[(size_t)r * KCL + (c - NIN - PROJW)];
    split_bf16(v, g_wchi[idx], g_wclo[idx]);
}

// ---------------- GEMM: BM=128 BN=64 BK=32, 256 threads, bf16 3-split -------
#define BM 128
#define BN 64
#define BK 32
#define APITCH 80u        // bytes/row smem A (64B data + 16B pad) -> ldmatrix conflict-free
#define BPITCH 144u       // bytes/row smem B (128B data + 16B pad)
#define A_BYTES (BM * APITCH)                  // 10240
#define B_BYTES (BK * BPITCH)                  // 4608
#define STAGE_BYTES (2u * A_BYTES + 2u * B_BYTES)  // 29696

__device__ __forceinline__ void load_stage(
    uint32_t sbuf,
    const __nv_bfloat16* __restrict__ Ahi, const __nv_bfloat16* __restrict__ Alo,
    const __nv_bfloat16* __restrict__ Bhi, const __nv_bfloat16* __restrict__ Blo,
    int m0, int n0, int k0, int ldA, int ldB, int tid)
{
    uint32_t sAhi = sbuf;
    uint32_t sAlo = sbuf + A_BYTES;
    uint32_t sBhi = sbuf + 2u * A_BYTES;
    uint32_t sBlo = sBhi + B_BYTES;

    // A tile: 128 rows x 32 bf16 (64B) -> 4 x 16B chunks/row, 512 chunks/split
#pragma unroll
    for (int i = 0; i < 2; ++i) {
        int c = tid + i * 256;
        int row = c >> 2;
        uint32_t cb = (uint32_t)(c & 3) << 4;
        size_t goff = ((size_t)(m0 + row) * ldA + k0) * 2 + cb;
        cpa16(sAhi + (uint32_t)row * APITCH + cb, (const char*)Ahi + goff);
        cpa16(sAlo + (uint32_t)row * APITCH + cb, (const char*)Alo + goff);
    }
    // B tile: 32 rows x 64 bf16 (128B) -> 8 chunks/row, 256 chunks/split
    {
        int row = tid >> 3;
        uint32_t cb = (uint32_t)(tid & 7) << 4;
        size_t goff = ((size_t)(k0 + row) * ldB + n0) * 2 + cb;
        cpa16(sBhi + (uint32_t)row * BPITCH + cb, (const char*)Bhi + goff);
        cpa16(sBlo + (uint32_t)row * BPITCH + cb, (const char*)Blo + goff);
    }
    asm volatile("cp.async.commit_group;\n");
}

// MODE 0: z = A@B + enc_b  -> out0 (fp32, ld=LAT, guard n<LAT) + split into g_zhi/g_zlo
// MODE 1: routed: n<204 -> x_bar(+dec_b); 204..283 -> g_proj; 284..299 -> logits(+pc_b)
template<int MODE>
__global__ __launch_bounds__(256)
void mma_gemm(const __nv_bfloat16* __restrict__ Ahi, const __nv_bfloat16* __restrict__ Alo,
              const __nv_bfloat16* __restrict__ Bhi, const __nv_bfloat16* __restrict__ Blo,
              int K, int ldA, int ldB,
              const float* __restrict__ bias0, const float* __restrict__ bias1,
              float* __restrict__ out0, float* __restrict__ out1)
{
    extern __shared__ char smem_raw[];
    const uint32_t sbase = (uint32_t)__cvta_generic_to_shared(smem_raw);

    const int tid  = threadIdx.x;
    const int lane = tid & 31;
    const int warp = tid >> 5;
    const int wm   = warp >> 2;   // 0..1 -> 64-row half
    const int wn   = warp & 3;    // 0..3 -> 16-col slice
    const int m0   = blockIdx.y * BM;
    const int n0   = blockIdx.x * BN;

    float acc[4][2][4];
#pragma unroll
    for (int i = 0; i < 4; ++i)
#pragma unroll
        for (int j = 0; j < 2; ++j)
#pragma unroll
            for (int e = 0; e < 4; ++e) acc[i][j][e] = 0.0f;

    const int T = K / BK;
    load_stage(sbase, Ahi, Alo, Bhi, Blo, m0, n0, 0, ldA, ldB, tid);

    for (int t = 0; t < T; ++t) {
        asm volatile("cp.async.wait_group 0;\n");
        __syncthreads();
        if (t + 1 < T)
            load_stage(sbase + ((uint32_t)((t + 1) & 1)) * STAGE_BYTES,
                       Ahi, Alo, Bhi, Blo, m0, n0, (t + 1) * BK, ldA, ldB, tid);

        const uint32_t sbuf = sbase + ((uint32_t)(t & 1)) * STAGE_BYTES;
        const uint32_t sAhi = sbuf;
        const uint32_t sAlo = sbuf + A_BYTES;
        const uint32_t sBhi = sbuf + 2u * A_BYTES;
        const uint32_t sBlo = sBhi + B_BYTES;

#pragma unroll
        for (int kk = 0; kk < 2; ++kk) {
            uint32_t ahi[4][4], alo[4][4], bhi[2][2], blo[2][2];
            // A fragments: lanes 0-7 rows0-7@klo, 8-15 rows8-15@klo, 16-23 rows0-7@khi, 24-31 rows8-15@khi
            const uint32_t arow = (uint32_t)(wm * 64 + (lane & 15));
            const uint32_t acol = ((uint32_t)(lane >> 4) << 4) + (uint32_t)kk * 32u;
#pragma unroll
            for (int mt = 0; mt < 4; ++mt) {
                uint32_t off = (arow + (uint32_t)mt * 16u) * APITCH + acol;
                ldmA(ahi[mt], sAhi + off);
                ldmA(alo[mt], sAlo + off);
            }
            // B fragments (trans): lanes 0-15 supply k rows
            const uint32_t brow = (uint32_t)(kk * 16 + (lane & 15));
#pragma unroll
            for (int nt = 0; nt < 2; ++nt) {
                uint32_t off = brow * BPITCH + (uint32_t)(wn * 32 + nt * 16);
                ldmBt(bhi[nt], sBhi + off);
                ldmBt(blo[nt], sBlo + off);
            }
#pragma unroll
            for (int mt = 0; mt < 4; ++mt)
#pragma unroll
                for (int nt = 0; nt < 2; ++nt) {
                    mma16816(acc[mt][nt], ahi[mt], bhi[nt]);
                    mma16816(acc[mt][nt], ahi[mt], blo[nt]);
                    mma16816(acc[mt][nt], alo[mt], bhi[nt]);
                }
        }
        __syncthreads();
    }

    // ---- epilogue ----
#pragma unroll
    for (int mt = 0; mt < 4; ++mt) {
        const int row0 = m0 + wm * 64 + mt * 16 + (lane >> 2);
#pragma unroll
        for (int nt = 0; nt < 2; ++nt) {
            const int col0 = n0 + wn * 16 + nt * 8 + (lane & 3) * 2;
#pragma unroll
            for (int e = 0; e < 4; ++e) {
                const int row = row0 + (e >> 1) * 8;
                const int col = col0 + (e & 1);
                const float v = acc[mt][nt][e];
                if (MODE == 0) {
                    if (col < LAT) {
                        float z = v + bias0[col];
                        size_t idx = (size_t)row * LAT + col;
                        out0[idx] = z;
                        split_bf16(z, g_zhi[idx], g_zlo[idx]);
                    }
                } else {
                    if (col < NIN) {
                        out0[(size_t)row * NIN + col] = v + bias0[col];
                    } else if (col < NIN + PROJW) {
                        g_proj[(size_t)row * PROJW + (col - NIN)] = v;
                    } else if (col < NCAT) {
                        out1[(size_t)row * KCL + (col - NIN - PROJW)] = v + bias1[col - NIN - PROJW];
                    }
                }
            }
        }
    }
}

// ---------------- soft subspace assignment ----------------
__global__ void s_kernel(float* __restrict__ s_out) {
    int row = blockIdx.x * blockDim.x + threadIdx.x;
    if (row >= NROWS) return;
    const float* p = g_proj + (size_t)row * PROJW;
    float sv[KCL];
    float tot = 0.0f;
#pragma unroll
    for (int i = 0; i < KCL; ++i) {
        float a = 0.0f;
#pragma unroll
        for (int j = 0; j < DSUB; ++j) {
            float v = p[i * DSUB + j];
            a = fmaf(v, v, a);
        }
        float si = (a + 25.0f) * (1.0f / 30.0f);   // (s + ETA*d)/((ETA+1)*d), ETA=5,d=5
        sv[i] = si;
        tot += si;
    }
    float inv = 1.0f / tot;
#pragma unroll
    for (int i = 0; i < KCL; ++i)
        s_out[(size_t)row * KCL + i] = sv[i] * inv;
}

// ---------------- launch ----------------
extern "C" void kernel_launch(void* const* d_in, const int* in_sizes, int n_in,
                              void* d_out, int out_size) {
    const float* x     = (const float*)d_in[0];
    const float* enc_W = (const float*)d_in[1];
    const float* enc_b = (const float*)d_in[2];
    const float* dec_W = (const float*)d_in[3];
    const float* dec_b = (const float*)d_in[4];
    const float* Dm    = (const float*)d_in[5];
    const float* pc_W  = (const float*)d_in[6];
    const float* pc_b  = (const float*)d_in[7];

    float* out   = (float*)d_out;
    float* xbar  = out;
    float* s     = out + S_OFF;
    float* z     = out + Z_OFF;
    float* logit = out + LOG_OFF;

    // scratch symbol addresses (host-side, capture-safe)
    __nv_bfloat16 *xhi, *xlo, *ewhi, *ewlo, *zhi, *zlo, *wchi, *wclo;
    cudaGetSymbolAddress((void**)&xhi,  g_xhi);
    cudaGetSymbolAddress((void**)&xlo,  g_xlo);
    cudaGetSymbolAddress((void**)&ewhi, g_ewhi);
    cudaGetSymbolAddress((void**)&ewlo, g_ewlo);
    cudaGetSymbolAddress((void**)&zhi,  g_zhi);
    cudaGetSymbolAddress((void**)&zlo,  g_zlo);
    cudaGetSymbolAddress((void**)&wchi, g_wchi);
    cudaGetSymbolAddress((void**)&wclo, g_wclo);

    cudaFuncSetAttribute(mma_gemm<0>, cudaFuncAttributeMaxDynamicSharedMemorySize, 2 * STAGE_BYTES);
    cudaFuncSetAttribute(mma_gemm<1>, cudaFuncAttributeMaxDynamicSharedMemorySize, 2 * STAGE_BYTES);

    // 1) split/pack operands to bf16 hi/lo
    conv_x_kernel<<<(NROWS * KPAD1 + 255) / 256, 256>>>(x);
    conv_ew_kernel<<<(KPAD1 * NPAD1 + 255) / 256, 256>>>(enc_W);
    conv_wc_kernel<<<(LAT * NCATP + 255) / 256, 256>>>(dec_W, Dm, pc_W);

    // 2) z = x @ enc_W + enc_b  (M=32768, N=1600(pad), K=224(pad))
    {
        dim3 grid(NPAD1 / BN, NROWS / BM);
        mma_gemm<0><<<grid, 256, 2 * STAGE_BYTES>>>(
            xhi, xlo, ewhi, ewlo, KPAD1, KPAD1, NPAD1,
            enc_b, nullptr, z, nullptr);
    }

    // 3) [x_bar | proj | logits] = z @ Wcat  (M=32768, N=320(pad), K=1568)
    {
        dim3 grid(NCATP / BN, NROWS / BM);
        mma_gemm<1><<<grid, 256, 2 * STAGE_BYTES>>>(
            zhi, zlo, wchi, wclo, LAT, LAT, NCATP,
            dec_b, pc_b, xbar, logit);
    }

    // 4) s from proj
    s_kernel<<<(NROWS + 255) / 256, 256>>>(s);
}

// round 14
// speedup vs baseline: 2.5722x; 1.0025x over previous
#include <cuda_runtime.h>
#include <cuda_bf16.h>
#include <cstdint>

// ---------------- problem constants ----------------
#define NROWS 32768
#define NIN   204
#define LAT   1568
#define KCL   16
#define DSUB  5
#define PROJW 80          // KCL*DSUB
#define NCAT  300         // 204+80+16
#define NCATP 320         // padded to BN multiple
#define KPAD1 224         // K for GEMM1 (204 -> 224, multiple of 32)
#define NPAD1 1600        // N for GEMM1 (1568 -> 1600)

// output layout: x_bar | s | z | logits
#define S_OFF   ((size_t)NROWS*NIN)
#define Z_OFF   (S_OFF + (size_t)NROWS*KCL)
#define LOG_OFF (Z_OFF + (size_t)NROWS*LAT)

// ---------------- scratch (device globals; no allocation allowed) ----------
__device__ __nv_bfloat16 g_xhi[(size_t)NROWS * KPAD1];
__device__ __nv_bfloat16 g_xlo[(size_t)NROWS * KPAD1];
__device__ __nv_bfloat16 g_ewhi[KPAD1 * NPAD1];
__device__ __nv_bfloat16 g_ewlo[KPAD1 * NPAD1];
__device__ __nv_bfloat16 g_zhi[(size_t)NROWS * LAT];
__device__ __nv_bfloat16 g_zlo[(size_t)NROWS * LAT];
__device__ __nv_bfloat16 g_wchi[LAT * NCATP];
__device__ __nv_bfloat16 g_wclo[LAT * NCATP];
__device__ float         g_proj[(size_t)NROWS * PROJW];

// ---------------- helpers ----------------
__device__ __forceinline__ void split_bf16(float v, __nv_bfloat16& h, __nv_bfloat16& l) {
    h = __float2bfloat16(v);
    l = __float2bfloat16(v - __bfloat162float(h));
}

__device__ __forceinline__ void cpa16(uint32_t dst, const void* src) {
    asm volatile("cp.async.cg.shared.global [%0], [%1], 16;\n" :: "r"(dst), "l"(src));
}

__device__ __forceinline__ void ldmA(uint32_t* r, uint32_t addr) {
    asm volatile("ldmatrix.sync.aligned.m8n8.x4.shared.b16 {%0,%1,%2,%3}, [%4];\n"
                 : "=r"(r[0]), "=r"(r[1]), "=r"(r[2]), "=r"(r[3]) : "r"(addr));
}
__device__ __forceinline__ void ldmBt(uint32_t* r, uint32_t addr) {
    asm volatile("ldmatrix.sync.aligned.m8n8.x2.trans.shared.b16 {%0,%1}, [%2];\n"
                 : "=r"(r[0]), "=r"(r[1]) : "r"(addr));
}
__device__ __forceinline__ void mma16816(float* c, const uint32_t* a, const uint32_t* b) {
    asm volatile("mma.sync.aligned.m16n8k16.row.col.f32.bf16.bf16.f32 "
                 "{%0,%1,%2,%3}, {%4,%5,%6,%7}, {%8,%9}, {%0,%1,%2,%3};\n"
                 : "+f"(c[0]), "+f"(c[1]), "+f"(c[2]), "+f"(c[3])
                 : "r"(a[0]), "r"(a[1]), "r"(a[2]), "r"(a[3]), "r"(b[0]), "r"(b[1]));
}

// ---------------- conversion / packing kernels ----------------
__global__ void conv_x_kernel(const float* __restrict__ x) {
    int idx = blockIdx.x * blockDim.x + threadIdx.x;
    if (idx >= NROWS * KPAD1) return;
    int r = idx / KPAD1, c = idx - r * KPAD1;
    float v = (c < NIN) ? x[(size_t)r * NIN + c] : 0.0f;
    split_bf16(v, g_xhi[idx], g_xlo[idx]);
}

__global__ void conv_ew_kernel(const float* __restrict__ w) {
    int idx = blockIdx.x * blockDim.x + threadIdx.x;
    if (idx >= KPAD1 * NPAD1) return;
    int r = idx / NPAD1, c = idx - r * NPAD1;
    float v = (r < NIN && c < LAT) ? w[(size_t)r * LAT + c] : 0.0f;
    split_bf16(v, g_ewhi[idx], g_ewlo[idx]);
}

__global__ void conv_wc_kernel(const float* __restrict__ decW,
                               const float* __restrict__ D,
                               const float* __restrict__ pcW) {
    int idx = blockIdx.x * blockDim.x + threadIdx.x;
    if (idx >= LAT * NCATP) return;
    int r = idx / NCATP, c = idx - r * NCATP;
    float v = 0.0f;
    if (c < NIN)              v = decW[(size_t)r * NIN + c];
    else if (c < NIN + PROJW) v = D[(size_t)r * PROJW + (c - NIN)];
    else if (c < NCAT)        v = pcW[(size_t)r * KCL + (c - NIN - PROJW)];
    split_bf16(v, g_wchi[idx], g_wclo[idx]);
}

// ---------------- GEMM: BM=128 BN=64 BK=32, 256 threads, bf16 3-split -------
#define BM 128
#define BN 64
#define BK 32
#define APITCH 80u        // bytes/row smem A (64B data + 16B pad) -> ldmatrix conflict-free
#define BPITCH 144u       // bytes/row smem B (128B data + 16B pad)
#define A_BYTES (BM * APITCH)                  // 10240
#define B_BYTES (BK * BPITCH)                  // 4608
#define STAGE_BYTES (2u * A_BYTES + 2u * B_BYTES)  // 29696

__device__ __forceinline__ void load_stage(
    uint32_t sbuf,
    const __nv_bfloat16* __restrict__ Ahi, const __nv_bfloat16* __restrict__ Alo,
    const __nv_bfloat16* __restrict__ Bhi, const __nv_bfloat16* __restrict__ Blo,
    int m0, int n0, int k0, int ldA, int ldB, int tid)
{
    uint32_t sAhi = sbuf;
    uint32_t sAlo = sbuf + A_BYTES;
    uint32_t sBhi = sbuf + 2u * A_BYTES;
    uint32_t sBlo = sBhi + B_BYTES;

    // A tile: 128 rows x 32 bf16 (64B) -> 4 x 16B chunks/row, 512 chunks/split
#pragma unroll
    for (int i = 0; i < 2; ++i) {
        int c = tid + i * 256;
        int row = c >> 2;
        uint32_t cb = (uint32_t)(c & 3) << 4;
        size_t goff = ((size_t)(m0 + row) * ldA + k0) * 2 + cb;
        cpa16(sAhi + (uint32_t)row * APITCH + cb, (const char*)Ahi + goff);
        cpa16(sAlo + (uint32_t)row * APITCH + cb, (const char*)Alo + goff);
    }
    // B tile: 32 rows x 64 bf16 (128B) -> 8 chunks/row, 256 chunks/split
    {
        int row = tid >> 3;
        uint32_t cb = (uint32_t)(tid & 7) << 4;
        size_t goff = ((size_t)(k0 + row) * ldB + n0) * 2 + cb;
        cpa16(sBhi + (uint32_t)row * BPITCH + cb, (const char*)Bhi + goff);
        cpa16(sBlo + (uint32_t)row * BPITCH + cb, (const char*)Blo + goff);
    }
    asm volatile("cp.async.commit_group;\n");
}

// MODE 0: z = A@B + enc_b  -> out0 (fp32, ld=LAT, guard n<LAT) + split into g_zhi/g_zlo
// MODE 1: routed: n<204 -> x_bar(+dec_b); 204..283 -> g_proj; 284..299 -> logits(+pc_b)
template<int MODE>
__global__ __launch_bounds__(256)
void mma_gemm(const __nv_bfloat16* __restrict__ Ahi, const __nv_bfloat16* __restrict__ Alo,
              const __nv_bfloat16* __restrict__ Bhi, const __nv_bfloat16* __restrict__ Blo,
              int K, int ldA, int ldB,
              const float* __restrict__ bias0, const float* __restrict__ bias1,
              float* __restrict__ out0, float* __restrict__ out1)
{
    extern __shared__ char smem_raw[];
    const uint32_t sbase = (uint32_t)__cvta_generic_to_shared(smem_raw);

    const int tid  = threadIdx.x;
    const int lane = tid & 31;
    const int warp = tid >> 5;
    const int wm   = warp >> 2;   // 0..1 -> 64-row half
    const int wn   = warp & 3;    // 0..3 -> 16-col slice
    const int m0   = blockIdx.y * BM;
    const int n0   = blockIdx.x * BN;

    float acc[4][2][4];
#pragma unroll
    for (int i = 0; i < 4; ++i)
#pragma unroll
        for (int j = 0; j < 2; ++j)
#pragma unroll
            for (int e = 0; e < 4; ++e) acc[i][j][e] = 0.0f;

    const int T = K / BK;
    load_stage(sbase, Ahi, Alo, Bhi, Blo, m0, n0, 0, ldA, ldB, tid);

    for (int t = 0; t < T; ++t) {
        asm volatile("cp.async.wait_group 0;\n");
        __syncthreads();
        if (t + 1 < T)
            load_stage(sbase + ((uint32_t)((t + 1) & 1)) * STAGE_BYTES,
                       Ahi, Alo, Bhi, Blo, m0, n0, (t + 1) * BK, ldA, ldB, tid);

        const uint32_t sbuf = sbase + ((uint32_t)(t & 1)) * STAGE_BYTES;
        const uint32_t sAhi = sbuf;
        const uint32_t sAlo = sbuf + A_BYTES;
        const uint32_t sBhi = sbuf + 2u * A_BYTES;
        const uint32_t sBlo = sBhi + B_BYTES;

#pragma unroll
        for (int kk = 0; kk < 2; ++kk) {
            uint32_t ahi[4][4], alo[4][4], bhi[2][2], blo[2][2];
            // A fragments: lanes 0-7 rows0-7@klo, 8-15 rows8-15@klo, 16-23 rows0-7@khi, 24-31 rows8-15@khi
            const uint32_t arow = (uint32_t)(wm * 64 + (lane & 15));
            const uint32_t acol = ((uint32_t)(lane >> 4) << 4) + (uint32_t)kk * 32u;
#pragma unroll
            for (int mt = 0; mt < 4; ++mt) {
                uint32_t off = (arow + (uint32_t)mt * 16u) * APITCH + acol;
                ldmA(ahi[mt], sAhi + off);
                ldmA(alo[mt], sAlo + off);
            }
            // B fragments (trans): lanes 0-15 supply k rows
            const uint32_t brow = (uint32_t)(kk * 16 + (lane & 15));
#pragma unroll
            for (int nt = 0; nt < 2; ++nt) {
                uint32_t off = brow * BPITCH + (uint32_t)(wn * 32 + nt * 16);
                ldmBt(bhi[nt], sBhi + off);
                ldmBt(blo[nt], sBlo + off);
            }
#pragma unroll
            for (int mt = 0; mt < 4; ++mt)
#pragma unroll
                for (int nt = 0; nt < 2; ++nt) {
                    mma16816(acc[mt][nt], ahi[mt], bhi[nt]);
                    mma16816(acc[mt][nt], ahi[mt], blo[nt]);
                    mma16816(acc[mt][nt], alo[mt], bhi[nt]);
                }
        }
        __syncthreads();
    }

    // ---- epilogue ----
#pragma unroll
    for (int mt = 0; mt < 4; ++mt) {
        const int row0 = m0 + wm * 64 + mt * 16 + (lane >> 2);
#pragma unroll
        for (int nt = 0; nt < 2; ++nt) {
            const int col0 = n0 + wn * 16 + nt * 8 + (lane & 3) * 2;
#pragma unroll
            for (int e = 0; e < 4; ++e) {
                const int row = row0 + (e >> 1) * 8;
                const int col = col0 + (e & 1);
                const float v = acc[mt][nt][e];
                if (MODE == 0) {
                    if (col < LAT) {
                        float z = v + bias0[col];
                        size_t idx = (size_t)row * LAT + col;
                        out0[idx] = z;
                        split_bf16(z, g_zhi[idx], g_zlo[idx]);
                    }
                } else {
                    if (col < NIN) {
                        out0[(size_t)row * NIN + col] = v + bias0[col];
                    } else if (col < NIN + PROJW) {
                        g_proj[(size_t)row * PROJW + (col - NIN)] = v;
                    } else if (col < NCAT) {
                        out1[(size_t)row * KCL + (col - NIN - PROJW)] = v + bias1[col - NIN - PROJW];
                    }
                }
            }
        }
    }
}

// ---------------- soft subspace assignment ----------------
__global__ void s_kernel(float* __restrict__ s_out) {
    int row = blockIdx.x * blockDim.x + threadIdx.x;
    if (row >= NROWS) return;
    const float* p = g_proj + (size_t)row * PROJW;
    float sv[KCL];
    float tot = 0.0f;
#pragma unroll
    for (int i = 0; i < KCL; ++i) {
        float a = 0.0f;
#pragma unroll
        for (int j = 0; j < DSUB; ++j) {
            float v = p[i * DSUB + j];
            a = fmaf(v, v, a);
        }
        float si = (a + 25.0f) * (1.0f / 30.0f);   // (s + ETA*d)/((ETA+1)*d), ETA=5,d=5
        sv[i] = si;
        tot += si;
    }
    float inv = 1.0f / tot;
#pragma unroll
    for (int i = 0; i < KCL; ++i)
        s_out[(size_t)row * KCL + i] = sv[i] * inv;
}

// ---------------- launch ----------------
extern "C" void kernel_launch(void* const* d_in, const int* in_sizes, int n_in,
                              void* d_out, int out_size) {
    const float* x     = (const float*)d_in[0];
    const float* enc_W = (const float*)d_in[1];
    const float* enc_b = (const float*)d_in[2];
    const float* dec_W = (const float*)d_in[3];
    const float* dec_b = (const float*)d_in[4];
    const float* Dm    = (const float*)d_in[5];
    const float* pc_W  = (const float*)d_in[6];
    const float* pc_b  = (const float*)d_in[7];

    float* out   = (float*)d_out;
    float* xbar  = out;
    float* s     = out + S_OFF;
    float* z     = out + Z_OFF;
    float* logit = out + LOG_OFF;

    // scratch symbol addresses (host-side, capture-safe)
    __nv_bfloat16 *xhi, *xlo, *ewhi, *ewlo, *zhi, *zlo, *wchi, *wclo;
    cudaGetSymbolAddress((void**)&xhi,  g_xhi);
    cudaGetSymbolAddress((void**)&xlo,  g_xlo);
    cudaGetSymbolAddress((void**)&ewhi, g_ewhi);
    cudaGetSymbolAddress((void**)&ewlo, g_ewlo);
    cudaGetSymbolAddress((void**)&zhi,  g_zhi);
    cudaGetSymbolAddress((void**)&zlo,  g_zlo);
    cudaGetSymbolAddress((void**)&wchi, g_wchi);
    cudaGetSymbolAddress((void**)&wclo, g_wclo);

    cudaFuncSetAttribute(mma_gemm<0>, cudaFuncAttributeMaxDynamicSharedMemorySize, 2 * STAGE_BYTES);
    cudaFuncSetAttribute(mma_gemm<1>, cudaFuncAttributeMaxDynamicSharedMemorySize, 2 * STAGE_BYTES);

    // 1) split/pack operands to bf16 hi/lo
    conv_x_kernel<<<(NROWS * KPAD1 + 255) / 256, 256>>>(x);
    conv_ew_kernel<<<(KPAD1 * NPAD1 + 255) / 256, 256>>>(enc_W);
    conv_wc_kernel<<<(LAT * NCATP + 255) / 256, 256>>>(dec_W, Dm, pc_W);

    // 2) z = x @ enc_W + enc_b  (M=32768, N=1600(pad), K=224(pad))
    {
        dim3 grid(NPAD1 / BN, NROWS / BM);
        mma_gemm<0><<<grid, 256, 2 * STAGE_BYTES>>>(
            xhi, xlo, ewhi, ewlo, KPAD1, KPAD1, NPAD1,
            enc_b, nullptr, z, nullptr);
    }

    // 3) [x_bar | proj | logits] = z @ Wcat  (M=32768, N=320(pad), K=1568)
    {
        dim3 grid(NCATP / BN, NROWS / BM);
        mma_gemm<1><<<grid, 256, 2 * STAGE_BYTES>>>(
            zhi, zlo, wchi, wclo, LAT, LAT, NCATP,
            dec_b, pc_b, xbar, logit);
    }

    // 4) s from proj
    s_kernel<<<(NROWS + 255) / 256, 256>>>(s);
}

// round 16
// speedup vs baseline: 4.1239x; 1.6032x over previous
#include <cuda_runtime.h>
#include <cuda_fp16.h>
#include <cstdint>

// ---------------- problem constants ----------------
#define NROWS 32768
#define NIN   204
#define LAT   1568
#define KCL   16
#define DSUB  5
#define PROJW 80
#define NCAT  300          // 204+80+16
#define KP1   224          // K for GEMM1 (204 -> 224, mult of 32)
#define NP1   1664         // N for GEMM1 (1568 -> 13*128)
#define KP2   1600         // K for GEMM2 (1568 -> 50*32)
#define NP2   320          // N for GEMM2 (300 -> 5*64)

#define WSCALE 64.0f       // B pre-scale (keeps fp16 lo-split normal)
#define INVSC  (1.0f/64.0f)

// output layout: x_bar | s | z | logits
#define S_OFF   ((size_t)NROWS*NIN)
#define Z_OFF   (S_OFF + (size_t)NROWS*KCL)
#define LOG_OFF (Z_OFF + (size_t)NROWS*LAT)

// ---------------- scratch (device globals) ----------------
__device__ __align__(256) __half g_xh [(size_t)NROWS * KP1];   // x fp16 (unsplit)
__device__ __align__(256) __half g_ewh[(size_t)KP1 * NP1];     // enc_W*64 hi  [K][N]
__device__ __align__(256) __half g_ewl[(size_t)KP1 * NP1];     // enc_W*64 lo
__device__ __align__(256) __half g_zh [(size_t)NROWS * KP2];   // z fp16 (unsplit)
__device__ __align__(256) __half g_wch[(size_t)KP2 * NP2];     // Wcat*64 hi  [K][N]
__device__ __align__(256) __half g_wcl[(size_t)KP2 * NP2];     // Wcat*64 lo
__device__ __align__(256) float  g_proj[(size_t)NROWS * PROJW];

// ---------------- PTX helpers ----------------
__device__ __forceinline__ void cpa16(uint32_t dst, const void* src) {
    asm volatile("cp.async.cg.shared.global [%0], [%1], 16;\n" :: "r"(dst), "l"(src));
}
__device__ __forceinline__ void ldmA4(uint32_t* r, uint32_t addr) {
    asm volatile("ldmatrix.sync.aligned.m8n8.x4.shared.b16 {%0,%1,%2,%3}, [%4];\n"
                 : "=r"(r[0]), "=r"(r[1]), "=r"(r[2]), "=r"(r[3]) : "r"(addr));
}
__device__ __forceinline__ void ldmB4t(uint32_t* r, uint32_t addr) {
    asm volatile("ldmatrix.sync.aligned.m8n8.x4.trans.shared.b16 {%0,%1,%2,%3}, [%4];\n"
                 : "=r"(r[0]), "=r"(r[1]), "=r"(r[2]), "=r"(r[3]) : "r"(addr));
}
__device__ __forceinline__ void mma_f16(float* c, const uint32_t* a, const uint32_t* b) {
    asm volatile("mma.sync.aligned.m16n8k16.row.col.f32.f16.f16.f32 "
                 "{%0,%1,%2,%3}, {%4,%5,%6,%7}, {%8,%9}, {%0,%1,%2,%3};\n"
                 : "+f"(c[0]), "+f"(c[1]), "+f"(c[2]), "+f"(c[3])
                 : "r"(a[0]), "r"(a[1]), "r"(a[2]), "r"(a[3]), "r"(b[0]), "r"(b[1]));
}

__device__ __forceinline__ void split_h(float v, __half& h, __half& l) {
    h = __float2half_rn(v);
    l = __float2half_rn(v - __half2float(h));
}

// ---------------- conversion / packing kernels ----------------
__global__ void conv_x(const float* __restrict__ x) {
    int idx = blockIdx.x * blockDim.x + threadIdx.x;
    if (idx >= NROWS * KP1) return;
    int r = idx / KP1, c = idx - r * KP1;
    float v = (c < NIN) ? x[(size_t)r * NIN + c] : 0.0f;
    g_xh[idx] = __float2half_rn(v);
}

__global__ void conv_ew(const float* __restrict__ w) {   // [204,1568] -> [224][1664] *64
    int idx = blockIdx.x * blockDim.x + threadIdx.x;
    if (idx >= KP1 * NP1) return;
    int k = idx / NP1, n = idx - k * NP1;
    float v = (k < NIN && n < LAT) ? w[(size_t)k * LAT + n] * WSCALE : 0.0f;
    split_h(v, g_ewh[idx], g_ewl[idx]);
}

__global__ void conv_wc(const float* __restrict__ decW, const float* __restrict__ Dm,
                        const float* __restrict__ pcW) { // -> [1600][320] *64
    int idx = blockIdx.x * blockDim.x + threadIdx.x;
    if (idx >= KP2 * NP2) return;
    int k = idx / NP2, n = idx - k * NP2;
    float v = 0.0f;
    if (k < LAT) {
        if (n < NIN)              v = decW[(size_t)k * NIN + n];
        else if (n < NIN + PROJW) v = Dm[(size_t)k * PROJW + (n - NIN)];
        else if (n < NCAT)        v = pcW[(size_t)k * KCL + (n - NIN - PROJW)];
    }
    split_h(v * WSCALE, g_wch[idx], g_wcl[idx]);
}

// ---------------- HMMA GEMM ----------------
// A: [M][K] fp16 (unsplit). B: [K][N] fp16 hi+lo (pre-scaled x64).
// Warp tile 64x32, 8 warps, BK=32, 4-stage cp.async ring.
// MODE 0: z epilogue (x1/64 + enc_b -> z fp32 out + z fp16 scratch, zero K-pad)
// MODE 1: routed epilogue (x_bar / g_proj / logits), all x1/64 (+bias)
template<int BM, int BN, int K, int LDA, int LDB, int MODE>
__global__ __launch_bounds__(256)
void hmma_gemm(const __half* __restrict__ Ah,
               const __half* __restrict__ Bh, const __half* __restrict__ Bl,
               const float* __restrict__ bias0, const float* __restrict__ bias1,
               float* __restrict__ out0, float* __restrict__ out1)
{
    constexpr int WN = BN / 32;                 // warps along N
    constexpr int T  = K / 32;                  // k-chunks
    constexpr uint32_t APITCH = 80;             // 64B data + 16B pad
    constexpr uint32_t BPITCH = BN * 2 + 16;    // BN fp16 + 16B pad
    constexpr uint32_t ASZ = (uint32_t)BM * APITCH;
    constexpr uint32_t BSZ = 32u * BPITCH;
    constexpr uint32_t STAGE = ASZ + 2u * BSZ;

    extern __shared__ char smem[];
    const uint32_t sbase = (uint32_t)__cvta_generic_to_shared(smem);

    const int tid  = threadIdx.x;
    const int lane = tid & 31;
    const int warp = tid >> 5;
    const int wm   = warp / WN;                 // 64-row group
    const int wn   = warp % WN;                 // 32-col group
    const int m0   = blockIdx.y * BM;
    const int n0   = blockIdx.x * BN;

    float acc[4][4][4];
#pragma unroll
    for (int i = 0; i < 4; ++i)
#pragma unroll
        for (int j = 0; j < 4; ++j)
#pragma unroll
            for (int e = 0; e < 4; ++e) acc[i][j][e] = 0.0f;

    // ---- stage loader ----
    auto load_chunk = [&](int stage, int k0) {
        const uint32_t sb = sbase + (uint32_t)stage * STAGE;
#pragma unroll
        for (int i = 0; i < BM * 4 / 256; ++i) {           // A: BM rows x 4 chunks
            int c = tid + i * 256;
            int row = c >> 2;
            uint32_t cb = (uint32_t)(c & 3) << 4;
            cpa16(sb + (uint32_t)row * APITCH + cb,
                  (const char*)Ah + (((size_t)(m0 + row) * LDA + k0) << 1) + cb);
        }
#pragma unroll
        for (int i = 0; i < 32 * (BN / 8) / 256; ++i) {    // B: 32 rows x BN/8 chunks, 2 splits
            int c = tid + i * 256;
            int row = c / (BN / 8);
            int cc  = c - row * (BN / 8);
            uint32_t cb = (uint32_t)cc << 4;
            size_t g = (((size_t)(k0 + row) * LDB + n0) << 1) + cb;
            cpa16(sb + ASZ + (uint32_t)row * BPITCH + cb,       (const char*)Bh + g);
            cpa16(sb + ASZ + BSZ + (uint32_t)row * BPITCH + cb, (const char*)Bl + g);
        }
        asm volatile("cp.async.commit_group;\n" ::: "memory");
    };

    // prologue: 3 stages in flight
    load_chunk(0, 0);
    load_chunk(1, 32);
    load_chunk(2, 64);

    for (int t = 0; t < T; ++t) {
        asm volatile("cp.async.wait_group 2;\n" ::: "memory");
        __syncthreads();
        if (t + 3 < T) load_chunk((t + 3) & 3, (t + 3) * 32);
        else           asm volatile("cp.async.commit_group;\n" ::: "memory");

        const uint32_t sb = sbase + (uint32_t)(t & 3) * STAGE;
#pragma unroll
        for (int kk = 0; kk < 2; ++kk) {
            uint32_t a[4][4];
            const uint32_t arow = (uint32_t)(wm * 64 + (lane & 15));
            const uint32_t acol = ((uint32_t)(lane >> 4) << 4) + (uint32_t)kk * 32u;
#pragma unroll
            for (int mt = 0; mt < 4; ++mt)
                ldmA4(a[mt], sb + (arow + (uint32_t)mt * 16u) * APITCH + acol);

            uint32_t bf[2][8];   // [split][2 regs x 4 n-frags]
            const uint32_t boff = ((uint32_t)(kk * 16 + (lane & 15))) * BPITCH
                                + (uint32_t)(wn * 64) + ((uint32_t)(lane >> 4) << 4);
            ldmB4t(&bf[0][0], sb + ASZ + boff);
            ldmB4t(&bf[0][4], sb + ASZ + boff + 32);
            ldmB4t(&bf[1][0], sb + ASZ + BSZ + boff);
            ldmB4t(&bf[1][4], sb + ASZ + BSZ + boff + 32);

#pragma unroll
            for (int mt = 0; mt < 4; ++mt)
#pragma unroll
                for (int nt = 0; nt < 4; ++nt) {
                    mma_f16(acc[mt][nt], a[mt], &bf[0][nt * 2]);
                    mma_f16(acc[mt][nt], a[mt], &bf[1][nt * 2]);
                }
        }
    }

    // ---- epilogue (acc * 1/64) ----
#pragma unroll
    for (int mt = 0; mt < 4; ++mt) {
        const int r0 = m0 + wm * 64 + mt * 16 + (lane >> 2);
#pragma unroll
        for (int nt = 0; nt < 4; ++nt) {
            const int c0 = n0 + wn * 32 + nt * 8 + (lane & 3) * 2;
#pragma unroll
            for (int h = 0; h < 2; ++h) {
                const int row = r0 + h * 8;
                const float v0 = acc[mt][nt][h * 2 + 0] * INVSC;
                const float v1 = acc[mt][nt][h * 2 + 1] * INVSC;
                if (MODE == 0) {
                    if (c0 < LAT) {                       // c0 even, LAT even: pair in-region
                        float z0 = v0 + __ldg(&bias0[c0]);
                        float z1 = v1 + __ldg(&bias0[c0 + 1]);
                        *reinterpret_cast<float2*>(out0 + (size_t)row * LAT + c0)
                            = make_float2(z0, z1);
                        *reinterpret_cast<__half2*>(&g_zh[(size_t)row * KP2 + c0])
                            = __floats2half2_rn(z0, z1);
                    } else if (c0 < KP2) {                // zero K-pad for GEMM2
                        *reinterpret_cast<__half2*>(&g_zh[(size_t)row * KP2 + c0])
                            = __floats2half2_rn(0.0f, 0.0f);
                    }
                } else {
#pragma unroll
                    for (int q = 0; q < 2; ++q) {
                        const int c = c0 + q;
                        const float v = q ? v1 : v0;
                        if (c < NIN) {
                            out0[(size_t)row * NIN + c] = v + __ldg(&bias0[c]);
                        } else if (c < NIN + PROJW) {
                            g_proj[(size_t)row * PROJW + (c - NIN)] = v;
                        } else if (c < NCAT) {
                            out1[(size_t)row * KCL + (c - NIN - PROJW)]
                                = v + __ldg(&bias1[c - NIN - PROJW]);
                        }
                    }
                }
            }
        }
    }
}

// ---------------- soft subspace assignment ----------------
__global__ void s_kernel(float* __restrict__ s_out) {
    int row = blockIdx.x * blockDim.x + threadIdx.x;
    if (row >= NROWS) return;
    const float* p = g_proj + (size_t)row * PROJW;
    float sv[KCL], tot = 0.0f;
#pragma unroll
    for (int i = 0; i < KCL; ++i) {
        float a = 0.0f;
#pragma unroll
        for (int j = 0; j < DSUB; ++j) {
            float v = p[i * DSUB + j];
            a = fmaf(v, v, a);
        }
        float si = (a + 25.0f) * (1.0f / 30.0f);   // (s+ETA*d)/((ETA+1)*d), ETA=5, d=5
        sv[i] = si;
        tot += si;
    }
    float inv = 1.0f / tot;
#pragma unroll
    for (int i = 0; i < KCL; ++i)
        s_out[(size_t)row * KCL + i] = sv[i] * inv;
}

// ---------------- launch ----------------
extern "C" void kernel_launch(void* const* d_in, const int* in_sizes, int n_in,
                              void* d_out, int out_size) {
    (void)in_sizes; (void)n_in; (void)out_size;
    const float* x     = (const float*)d_in[0];
    const float* enc_W = (const float*)d_in[1];
    const float* enc_b = (const float*)d_in[2];
    const float* dec_W = (const float*)d_in[3];
    const float* dec_b = (const float*)d_in[4];
    const float* Dm    = (const float*)d_in[5];
    const float* pc_W  = (const float*)d_in[6];
    const float* pc_b  = (const float*)d_in[7];

    float* out   = (float*)d_out;
    float* xbar  = out;
    float* s     = out + S_OFF;
    float* z     = out + Z_OFF;
    float* logit = out + LOG_OFF;

    __half *xh, *ewh, *ewl, *zh, *wch, *wcl;
    cudaGetSymbolAddress((void**)&xh,  g_xh);
    cudaGetSymbolAddress((void**)&ewh, g_ewh);
    cudaGetSymbolAddress((void**)&ewl, g_ewl);
    cudaGetSymbolAddress((void**)&zh,  g_zh);
    cudaGetSymbolAddress((void**)&wch, g_wch);
    cudaGetSymbolAddress((void**)&wcl, g_wcl);

    // stage = BM*80 + 2*32*(BN*2+16); 4 stages
    constexpr uint32_t SM1 = 4u * (128u * 80u + 2u * 32u * (128u * 2u + 16u)); // 110592
    constexpr uint32_t SM2 = 4u * (256u * 80u + 2u * 32u * (64u  * 2u + 16u)); // 118784
    cudaFuncSetAttribute((const void*)hmma_gemm<128,128,KP1,KP1,NP1,0>,
                         cudaFuncAttributeMaxDynamicSharedMemorySize, SM1);
    cudaFuncSetAttribute((const void*)hmma_gemm<256,64,KP2,KP2,NP2,1>,
                         cudaFuncAttributeMaxDynamicSharedMemorySize, SM2);

    // 1) convert/pack
    conv_x <<<(NROWS * KP1 + 255) / 256, 256>>>(x);
    conv_ew<<<(KP1 * NP1 + 255) / 256, 256>>>(enc_W);
    conv_wc<<<(KP2 * NP2 + 255) / 256, 256>>>(dec_W, Dm, pc_W);

    // 2) z = x @ enc_W + enc_b   (M=32768, N=1664, K=224)
    {
        dim3 grid(NP1 / 128, NROWS / 128);
        hmma_gemm<128,128,KP1,KP1,NP1,0><<<grid, 256, SM1>>>(
            xh, ewh, ewl, enc_b, nullptr, z, nullptr);
    }
    // 3) [x_bar | proj | logits] = z @ Wcat   (M=32768, N=320, K=1600)
    {
        dim3 grid(NP2 / 64, NROWS / 256);
        hmma_gemm<256,64,KP2,KP2,NP2,1><<<grid, 256, SM2>>>(
            zh, wch, wcl, dec_b, pc_b, xbar, logit);
    }
    // 4) s from proj
    s_kernel<<<(NROWS + 255) / 256, 256>>>(s);
}

// round 17
// speedup vs baseline: 4.7313x; 1.1473x over previous
#include <cuda_runtime.h>
#include <cuda_fp16.h>
#include <cstdint>

// ---------------- problem constants ----------------
#define NROWS 32768
#define NIN   204
#define LAT   1568
#define KCL   16
#define DSUB  5
#define PROJW 80
#define NCAT  300          // 204+80+16
#define KP1   224          // K for GEMM1 (204 -> 224, mult of 32)
#define NP1   1664         // N for GEMM1 (1568 -> 13*128)
#define KP2   1600         // K for GEMM2 (1568 -> 50*32)
#define NP2   320          // N for GEMM2 (300 -> 5*64)

#define WSCALE 64.0f       // B pre-scale (keeps fp16 lo-split normal)
#define INVSC  (1.0f/64.0f)

// output layout: x_bar | s | z | logits
#define S_OFF   ((size_t)NROWS*NIN)
#define Z_OFF   (S_OFF + (size_t)NROWS*KCL)
#define LOG_OFF (Z_OFF + (size_t)NROWS*LAT)

// ---------------- scratch (device globals) ----------------
__device__ __align__(256) __half g_xh [(size_t)NROWS * KP1];   // x fp16 (unsplit)
__device__ __align__(256) __half g_ewh[(size_t)KP1 * NP1];     // enc_W*64 hi  [K][N]
__device__ __align__(256) __half g_ewl[(size_t)KP1 * NP1];     // enc_W*64 lo
__device__ __align__(256) __half g_zh [(size_t)NROWS * KP2];   // z fp16 (unsplit)
__device__ __align__(256) __half g_wch[(size_t)KP2 * NP2];     // Wcat*64 hi  [K][N]
__device__ __align__(256) __half g_wcl[(size_t)KP2 * NP2];     // Wcat*64 lo
__device__ __align__(256) float  g_proj[(size_t)NROWS * PROJW];

// ---------------- PTX helpers ----------------
__device__ __forceinline__ void cpa16(uint32_t dst, const void* src) {
    asm volatile("cp.async.cg.shared.global [%0], [%1], 16;\n" :: "r"(dst), "l"(src));
}
__device__ __forceinline__ void ldmA4(uint32_t* r, uint32_t addr) {
    asm volatile("ldmatrix.sync.aligned.m8n8.x4.shared.b16 {%0,%1,%2,%3}, [%4];\n"
                 : "=r"(r[0]), "=r"(r[1]), "=r"(r[2]), "=r"(r[3]) : "r"(addr));
}
__device__ __forceinline__ void ldmB4t(uint32_t* r, uint32_t addr) {
    asm volatile("ldmatrix.sync.aligned.m8n8.x4.trans.shared.b16 {%0,%1,%2,%3}, [%4];\n"
                 : "=r"(r[0]), "=r"(r[1]), "=r"(r[2]), "=r"(r[3]) : "r"(addr));
}
__device__ __forceinline__ void mma_f16(float* c, const uint32_t* a, const uint32_t* b) {
    asm volatile("mma.sync.aligned.m16n8k16.row.col.f32.f16.f16.f32 "
                 "{%0,%1,%2,%3}, {%4,%5,%6,%7}, {%8,%9}, {%0,%1,%2,%3};\n"
                 : "+f"(c[0]), "+f"(c[1]), "+f"(c[2]), "+f"(c[3])
                 : "r"(a[0]), "r"(a[1]), "r"(a[2]), "r"(a[3]), "r"(b[0]), "r"(b[1]));
}

__device__ __forceinline__ void split_h(float v, __half& h, __half& l) {
    h = __float2half_rn(v);
    l = __float2half_rn(v - __half2float(h));
}

// ---------------- conversion / packing kernels ----------------
__global__ void conv_x(const float* __restrict__ x) {
    int idx = blockIdx.x * blockDim.x + threadIdx.x;
    if (idx >= NROWS * KP1) return;
    int r = idx / KP1, c = idx - r * KP1;
    float v = (c < NIN) ? x[(size_t)r * NIN + c] : 0.0f;
    g_xh[idx] = __float2half_rn(v);
}

__global__ void conv_ew(const float* __restrict__ w) {   // [204,1568] -> [224][1664] *64
    int idx = blockIdx.x * blockDim.x + threadIdx.x;
    if (idx >= KP1 * NP1) return;
    int k = idx / NP1, n = idx - k * NP1;
    float v = (k < NIN && n < LAT) ? w[(size_t)k * LAT + n] * WSCALE : 0.0f;
    split_h(v, g_ewh[idx], g_ewl[idx]);
}

__global__ void conv_wc(const float* __restrict__ decW, const float* __restrict__ Dm,
                        const float* __restrict__ pcW) { // -> [1600][320] *64
    int idx = blockIdx.x * blockDim.x + threadIdx.x;
    if (idx >= KP2 * NP2) return;
    int k = idx / NP2, n = idx - k * NP2;
    float v = 0.0f;
    if (k < LAT) {
        if (n < NIN)              v = decW[(size_t)k * NIN + n];
        else if (n < NIN + PROJW) v = Dm[(size_t)k * PROJW + (n - NIN)];
        else if (n < NCAT)        v = pcW[(size_t)k * KCL + (n - NIN - PROJW)];
    }
    split_h(v * WSCALE, g_wch[idx], g_wcl[idx]);
}

// ---------------- HMMA GEMM ----------------
// A: [M][K] fp16 (unsplit). B: [K][N] fp16 hi+lo (pre-scaled x64).
// Warp tile 64x32, 8 warps, BK=32, 3-stage cp.async ring, 2 CTAs/SM.
// MODE 0: z epilogue (x1/64 + enc_b -> z fp32 out + z fp16 scratch, zero K-pad)
// MODE 1: routed epilogue (x_bar / g_proj / logits), all x1/64 (+bias)
template<int BM, int BN, int K, int LDA, int LDB, int MODE>
__global__ __launch_bounds__(256, 2)
void hmma_gemm(const __half* __restrict__ Ah,
               const __half* __restrict__ Bh, const __half* __restrict__ Bl,
               const float* __restrict__ bias0, const float* __restrict__ bias1,
               float* __restrict__ out0, float* __restrict__ out1)
{
    constexpr int WN = BN / 32;                 // warps along N
    constexpr int T  = K / 32;                  // k-chunks
    constexpr uint32_t APITCH = 80;             // 64B data + 16B pad
    constexpr uint32_t BPITCH = BN * 2 + 16;    // BN fp16 + 16B pad
    constexpr uint32_t ASZ = (uint32_t)BM * APITCH;
    constexpr uint32_t BSZ = 32u * BPITCH;
    constexpr uint32_t STAGE = ASZ + 2u * BSZ;

    extern __shared__ char smem[];
    const uint32_t sbase = (uint32_t)__cvta_generic_to_shared(smem);

    const int tid  = threadIdx.x;
    const int lane = tid & 31;
    const int warp = tid >> 5;
    const int wm   = warp / WN;                 // 64-row group
    const int wn   = warp % WN;                 // 32-col group
    const int m0   = blockIdx.y * BM;
    const int n0   = blockIdx.x * BN;

    float acc[4][4][4];
#pragma unroll
    for (int i = 0; i < 4; ++i)
#pragma unroll
        for (int j = 0; j < 4; ++j)
#pragma unroll
            for (int e = 0; e < 4; ++e) acc[i][j][e] = 0.0f;

    // ---- stage loader (one commit group per chunk) ----
    auto load_chunk = [&](int stage, int k0) {
        const uint32_t sb = sbase + (uint32_t)stage * STAGE;
#pragma unroll
        for (int i = 0; i < BM * 4 / 256; ++i) {           // A: BM rows x 4 chunks
            int c = tid + i * 256;
            int row = c >> 2;
            uint32_t cb = (uint32_t)(c & 3) << 4;
            cpa16(sb + (uint32_t)row * APITCH + cb,
                  (const char*)Ah + (((size_t)(m0 + row) * LDA + k0) << 1) + cb);
        }
#pragma unroll
        for (int i = 0; i < 32 * (BN / 8) / 256; ++i) {    // B: 32 rows x BN/8 chunks, 2 splits
            int c = tid + i * 256;
            int row = c / (BN / 8);
            int cc  = c - row * (BN / 8);
            uint32_t cb = (uint32_t)cc << 4;
            size_t g = (((size_t)(k0 + row) * LDB + n0) << 1) + cb;
            cpa16(sb + ASZ + (uint32_t)row * BPITCH + cb,       (const char*)Bh + g);
            cpa16(sb + ASZ + BSZ + (uint32_t)row * BPITCH + cb, (const char*)Bl + g);
        }
        asm volatile("cp.async.commit_group;\n" ::: "memory");
    };

    // 3-stage ring: prologue loads chunks 0,1 into stages 0,1.
    load_chunk(0, 0);
    load_chunk(1, 32);

    int stage = 0;   // stage holding chunk t
    for (int t = 0; t < T; ++t) {
        // chunk t's group must be complete; chunk t+1 may remain outstanding
        if (t + 1 < T) asm volatile("cp.async.wait_group 1;\n" ::: "memory");
        else           asm volatile("cp.async.wait_group 0;\n" ::: "memory");
        __syncthreads();
        // stage (t+2)%3 == (t-1)%3 was fully consumed in iter t-1 (pre-barrier)
        if (t + 2 < T) {
            int ns = stage + 2; if (ns >= 3) ns -= 3;
            load_chunk(ns, (t + 2) * 32);
        }

        const uint32_t sb = sbase + (uint32_t)stage * STAGE;
#pragma unroll
        for (int kk = 0; kk < 2; ++kk) {
            uint32_t a[4][4];
            const uint32_t arow = (uint32_t)(wm * 64 + (lane & 15));
            const uint32_t acol = ((uint32_t)(lane >> 4) << 4) + (uint32_t)kk * 32u;
#pragma unroll
            for (int mt = 0; mt < 4; ++mt)
                ldmA4(a[mt], sb + (arow + (uint32_t)mt * 16u) * APITCH + acol);

            uint32_t bf[2][8];   // [split][2 regs x 4 n-frags]
            const uint32_t boff = ((uint32_t)(kk * 16 + (lane & 15))) * BPITCH
                                + (uint32_t)(wn * 64) + ((uint32_t)(lane >> 4) << 4);
            ldmB4t(&bf[0][0], sb + ASZ + boff);
            ldmB4t(&bf[0][4], sb + ASZ + boff + 32);
            ldmB4t(&bf[1][0], sb + ASZ + BSZ + boff);
            ldmB4t(&bf[1][4], sb + ASZ + BSZ + boff + 32);

#pragma unroll
            for (int mt = 0; mt < 4; ++mt)
#pragma unroll
                for (int nt = 0; nt < 4; ++nt) {
                    mma_f16(acc[mt][nt], a[mt], &bf[0][nt * 2]);
                    mma_f16(acc[mt][nt], a[mt], &bf[1][nt * 2]);
                }
        }
        if (++stage >= 3) stage = 0;
    }

    // ---- epilogue (acc * 1/64) ----
#pragma unroll
    for (int mt = 0; mt < 4; ++mt) {
        const int r0 = m0 + wm * 64 + mt * 16 + (lane >> 2);
#pragma unroll
        for (int nt = 0; nt < 4; ++nt) {
            const int c0 = n0 + wn * 32 + nt * 8 + (lane & 3) * 2;
#pragma unroll
            for (int h = 0; h < 2; ++h) {
                const int row = r0 + h * 8;
                const float v0 = acc[mt][nt][h * 2 + 0] * INVSC;
                const float v1 = acc[mt][nt][h * 2 + 1] * INVSC;
                if (MODE == 0) {
                    if (c0 < LAT) {                       // c0 even, LAT even: pair in-region
                        float z0 = v0 + __ldg(&bias0[c0]);
                        float z1 = v1 + __ldg(&bias0[c0 + 1]);
                        *reinterpret_cast<float2*>(out0 + (size_t)row * LAT + c0)
                            = make_float2(z0, z1);
                        *reinterpret_cast<__half2*>(&g_zh[(size_t)row * KP2 + c0])
                            = __floats2half2_rn(z0, z1);
                    } else if (c0 < KP2) {                // zero K-pad for GEMM2
                        *reinterpret_cast<__half2*>(&g_zh[(size_t)row * KP2 + c0])
                            = __floats2half2_rn(0.0f, 0.0f);
                    }
                } else {
#pragma unroll
                    for (int q = 0; q < 2; ++q) {
                        const int c = c0 + q;
                        const float v = q ? v1 : v0;
                        if (c < NIN) {
                            out0[(size_t)row * NIN + c] = v + __ldg(&bias0[c]);
                        } else if (c < NIN + PROJW) {
                            g_proj[(size_t)row * PROJW + (c - NIN)] = v;
                        } else if (c < NCAT) {
                            out1[(size_t)row * KCL + (c - NIN - PROJW)]
                                = v + __ldg(&bias1[c - NIN - PROJW]);
                        }
                    }
                }
            }
        }
    }
}

// ---------------- soft subspace assignment ----------------
__global__ void s_kernel(float* __restrict__ s_out) {
    int row = blockIdx.x * blockDim.x + threadIdx.x;
    if (row >= NROWS) return;
    const float* p = g_proj + (size_t)row * PROJW;
    float sv[KCL], tot = 0.0f;
#pragma unroll
    for (int i = 0; i < KCL; ++i) {
        float a = 0.0f;
#pragma unroll
        for (int j = 0; j < DSUB; ++j) {
            float v = p[i * DSUB + j];
            a = fmaf(v, v, a);
        }
        float si = (a + 25.0f) * (1.0f / 30.0f);   // (s+ETA*d)/((ETA+1)*d), ETA=5, d=5
        sv[i] = si;
        tot += si;
    }
    float inv = 1.0f / tot;
#pragma unroll
    for (int i = 0; i < KCL; ++i)
        s_out[(size_t)row * KCL + i] = sv[i] * inv;
}

// ---------------- launch ----------------
extern "C" void kernel_launch(void* const* d_in, const int* in_sizes, int n_in,
                              void* d_out, int out_size) {
    (void)in_sizes; (void)n_in; (void)out_size;
    const float* x     = (const float*)d_in[0];
    const float* enc_W = (const float*)d_in[1];
    const float* enc_b = (const float*)d_in[2];
    const float* dec_W = (const float*)d_in[3];
    const float* dec_b = (const float*)d_in[4];
    const float* Dm    = (const float*)d_in[5];
    const float* pc_W  = (const float*)d_in[6];
    const float* pc_b  = (const float*)d_in[7];

    float* out   = (float*)d_out;
    float* xbar  = out;
    float* s     = out + S_OFF;
    float* z     = out + Z_OFF;
    float* logit = out + LOG_OFF;

    __half *xh, *ewh, *ewl, *zh, *wch, *wcl;
    cudaGetSymbolAddress((void**)&xh,  g_xh);
    cudaGetSymbolAddress((void**)&ewh, g_ewh);
    cudaGetSymbolAddress((void**)&ewl, g_ewl);
    cudaGetSymbolAddress((void**)&zh,  g_zh);
    cudaGetSymbolAddress((void**)&wch, g_wch);
    cudaGetSymbolAddress((void**)&wcl, g_wcl);

    // stage = BM*80 + 2*32*(BN*2+16); 3 stages; 2 CTAs/SM
    constexpr uint32_t SM1 = 3u * (128u * 80u + 2u * 32u * (128u * 2u + 16u)); // 82944
    constexpr uint32_t SM2 = 3u * (256u * 80u + 2u * 32u * (64u  * 2u + 16u)); // 89088
    cudaFuncSetAttribute((const void*)hmma_gemm<128,128,KP1,KP1,NP1,0>,
                         cudaFuncAttributeMaxDynamicSharedMemorySize, SM1);
    cudaFuncSetAttribute((const void*)hmma_gemm<256,64,KP2,KP2,NP2,1>,
                         cudaFuncAttributeMaxDynamicSharedMemorySize, SM2);

    // 1) convert/pack
    conv_x <<<(NROWS * KP1 + 255) / 256, 256>>>(x);
    conv_ew<<<(KP1 * NP1 + 255) / 256, 256>>>(enc_W);
    conv_wc<<<(KP2 * NP2 + 255) / 256, 256>>>(dec_W, Dm, pc_W);

    // 2) z = x @ enc_W + enc_b   (M=32768, N=1664, K=224)
    {
        dim3 grid(NP1 / 128, NROWS / 128);
        hmma_gemm<128,128,KP1,KP1,NP1,0><<<grid, 256, SM1>>>(
            xh, ewh, ewl, enc_b, nullptr, z, nullptr);
    }
    // 3) [x_bar | proj | logits] = z @ Wcat   (M=32768, N=320, K=1600)
    {
        dim3 grid(NP2 / 64, NROWS / 256);
        hmma_gemm<256,64,KP2,KP2,NP2,1><<<grid, 256, SM2>>>(
            zh, wch, wcl, dec_b, pc_b, xbar, logit);
    }
    // 4) s from proj
    s_kernel<<<(NROWS + 255) / 256, 256>>>(s);
}